// round 1
// baseline (speedup 1.0000x reference)
#include <cuda_runtime.h>
#include <math.h>

// Problem constants
#define B_ 2
#define T_ 2048
#define C_ 2048
#define H_ 16
#define HS_ 128
#define AL_ 10
#define KDIM 2048          // reduction dim for both GEMMs
#define M_ROWS 4096        // B*T

#define NEG_BIG (-1e30f)

// ---------------- scratch (static device globals: allowed) ----------------
__device__ float g_Q[B_*H_*T_*HS_];   // roped Q, (b,h,t,d)
__device__ float g_K[B_*H_*T_*HS_];   // roped K
__device__ float g_V[B_*H_*T_*HS_];
__device__ float g_Y[M_ROWS*C_];      // attention output, (b*T+t, h*HS+d)
__device__ float g_AK[H_*AL_*HS_];    // adapter keys  (h, j, d)
__device__ float g_AV[H_*AL_*HS_];    // adapter values

// ======================================================================
// SGEMM NT: C[m][n] = sum_k A[m][k]*Bw[n][k].
// 128x128x16 tile, 256 threads, 8x8 micro-tile.
// MODE 0: QKV -> rope + scatter to g_Q/g_K/g_V.  MODE 1: plain write to Cout.
// ======================================================================
template<int MODE>
__global__ __launch_bounds__(256) void sgemm_nt(
    const float* __restrict__ A, const float* __restrict__ Bw,
    const float* __restrict__ rope, float* __restrict__ Cout)
{
    __shared__ float As[16][132];
    __shared__ float Bs[16][132];

    const int tid = threadIdx.x;
    const int tx = tid & 15, ty = tid >> 4;
    const int bm = blockIdx.y << 7;
    const int bn = blockIdx.x << 7;
    const int lr = tid >> 2;          // 0..63
    const int lk = (tid & 3) << 2;    // 0,4,8,12

    const float* Arow0 = A  + (bm + lr)      * KDIM + lk;
    const float* Arow1 = A  + (bm + lr + 64) * KDIM + lk;
    const float* Brow0 = Bw + (bn + lr)      * KDIM + lk;
    const float* Brow1 = Bw + (bn + lr + 64) * KDIM + lk;

    float acc[8][8] = {};

    for (int k0 = 0; k0 < KDIM; k0 += 16) {
        float4 a0 = *(const float4*)(Arow0 + k0);
        float4 a1 = *(const float4*)(Arow1 + k0);
        float4 b0 = *(const float4*)(Brow0 + k0);
        float4 b1 = *(const float4*)(Brow1 + k0);
        __syncthreads();
        As[lk+0][lr]    = a0.x; As[lk+1][lr]    = a0.y; As[lk+2][lr]    = a0.z; As[lk+3][lr]    = a0.w;
        As[lk+0][lr+64] = a1.x; As[lk+1][lr+64] = a1.y; As[lk+2][lr+64] = a1.z; As[lk+3][lr+64] = a1.w;
        Bs[lk+0][lr]    = b0.x; Bs[lk+1][lr]    = b0.y; Bs[lk+2][lr]    = b0.z; Bs[lk+3][lr]    = b0.w;
        Bs[lk+0][lr+64] = b1.x; Bs[lk+1][lr+64] = b1.y; Bs[lk+2][lr+64] = b1.z; Bs[lk+3][lr+64] = b1.w;
        __syncthreads();
        #pragma unroll
        for (int kk = 0; kk < 16; kk++) {
            float af[8], bf[8];
            *(float4*)(af)   = *(const float4*)&As[kk][ty<<2];
            *(float4*)(af+4) = *(const float4*)&As[kk][(ty<<2)+64];
            *(float4*)(bf)   = *(const float4*)&Bs[kk][tx<<2];
            *(float4*)(bf+4) = *(const float4*)&Bs[kk][(tx<<2)+64];
            #pragma unroll
            for (int i = 0; i < 8; i++)
                #pragma unroll
                for (int j = 0; j < 8; j++)
                    acc[i][j] += af[i] * bf[j];
        }
    }

    #pragma unroll
    for (int gi = 0; gi < 2; gi++) {
        #pragma unroll
        for (int ii = 0; ii < 4; ii++) {
            const int i = gi*4 + ii;
            const int m = bm + gi*64 + (ty<<2) + ii;
            #pragma unroll
            for (int gj = 0; gj < 2; gj++) {
                const int ncol = bn + gj*64 + (tx<<2);
                float v0 = acc[i][gj*4+0], v1 = acc[i][gj*4+1];
                float v2 = acc[i][gj*4+2], v3 = acc[i][gj*4+3];
                if (MODE == 0) {
                    const int b   = m >> 11, t = m & 2047;
                    const int sel = ncol >> 11;          // 0=q 1=k 2=v
                    const int rem = ncol & 2047;
                    const int hh  = rem >> 7, d = rem & 127;
                    if (sel < 2) {
                        // rope: pairs (d,d+1), (d+2,d+3); rope row = t*128
                        const float* rp = rope + t*128 + d;
                        float c0 = rp[0], s0 = rp[1], c1 = rp[2], s1 = rp[3];
                        float r0 = v0*c0 - v1*s0;
                        float r1 = v1*c0 + v0*s0;
                        float r2 = v2*c1 - v3*s1;
                        float r3 = v3*c1 + v2*s1;
                        v0 = r0; v1 = r1; v2 = r2; v3 = r3;
                    }
                    float* dst = (sel == 0 ? g_Q : (sel == 1 ? g_K : g_V))
                               + ((b*H_ + hh)*T_ + t)*HS_ + d;
                    *(float4*)dst = make_float4(v0, v1, v2, v3);
                } else {
                    *(float4*)(Cout + m*C_ + ncol) = make_float4(v0, v1, v2, v3);
                }
            }
        }
    }
}

// ======================================================================
// Adapter K/V: pqkv = adapter_emb @ W_attn.T, keep k & v parts.
// One block per output column n' = 2048 + blockIdx.x.
// ======================================================================
__global__ __launch_bounds__(128) void adapter_kv(
    const float* __restrict__ W, const float* __restrict__ emb)
{
    const int bx = blockIdx.x;            // 0..4095
    const int np = 2048 + bx;
    const float* wrow = W + (long)np * KDIM;

    float part[AL_] = {};
    for (int k = threadIdx.x; k < KDIM; k += 128) {
        float w = wrow[k];
        #pragma unroll
        for (int j = 0; j < AL_; j++) part[j] += w * emb[j*KDIM + k];
    }
    #pragma unroll
    for (int j = 0; j < AL_; j++)
        #pragma unroll
        for (int off = 16; off; off >>= 1)
            part[j] += __shfl_xor_sync(0xffffffffu, part[j], off);

    __shared__ float red[AL_][4];
    const int w = threadIdx.x >> 5, lane = threadIdx.x & 31;
    if (lane == 0)
        #pragma unroll
        for (int j = 0; j < AL_; j++) red[j][w] = part[j];
    __syncthreads();
    if (threadIdx.x < AL_) {
        const int j = threadIdx.x;
        float s = red[j][0] + red[j][1] + red[j][2] + red[j][3];
        const int isv = bx >> 11;         // 0 = k-part, 1 = v-part
        const int nn  = bx & 2047;
        const int h   = nn >> 7, d = nn & 127;
        float* dst = isv ? g_AV : g_AK;
        dst[(h*AL_ + j)*HS_ + d] = s;
    }
}

// ======================================================================
// Flash attention (fp32, causal) with fused adapter attention + gating.
// BM=64, BN=64, 256 threads (16x16). Dynamic smem = 129280 B.
// ======================================================================
#define QT_LD 68
#define SS_LD 65
#define FLASH_SMEM_FLOATS (128*QT_LD*2 + 64*128 + 64*SS_LD + 2*AL_*HS_)
#define FLASH_SMEM_BYTES  (FLASH_SMEM_FLOATS*4)

__global__ __launch_bounds__(256, 1) void flash_kernel(const float* __restrict__ gating)
{
    extern __shared__ float sm[];
    float* Qt  = sm;                  // [128][68]  (d-major)
    float* Kt  = Qt  + 128*QT_LD;     // [128][68]
    float* Vs  = Kt  + 128*QT_LD;     // [64][128]
    float* Ss  = Vs  + 64*128;        // [64][65]   P tile
    float* AKs = Ss  + 64*SS_LD;      // [10][128]
    float* AVs = AKs + AL_*HS_;       // [10][128]

    const int tid = threadIdx.x;
    const int tx = tid & 15, ty = tid >> 4;
    const int qb = blockIdx.x;
    const int bh = blockIdx.y;
    const int h  = bh & 15;

    const float* Qg = g_Q + bh*T_*HS_ + qb*64*HS_;
    const float* Kg = g_K + bh*T_*HS_;
    const float* Vg = g_V + bh*T_*HS_;

    // load Q tile transposed
    #pragma unroll
    for (int f = 0; f < 8; f++) {
        int idx = tid + f*256;
        int row = idx >> 5, c4 = (idx & 31) << 2;
        float4 q = *(const float4*)(Qg + row*HS_ + c4);
        Qt[(c4+0)*QT_LD + row] = q.x; Qt[(c4+1)*QT_LD + row] = q.y;
        Qt[(c4+2)*QT_LD + row] = q.z; Qt[(c4+3)*QT_LD + row] = q.w;
    }
    // adapter tiles
    {
        const float4* AKg = (const float4*)(g_AK + h*AL_*HS_);
        const float4* AVg = (const float4*)(g_AV + h*AL_*HS_);
        for (int idx = tid; idx < AL_*HS_/4; idx += 256) {
            ((float4*)AKs)[idx] = AKg[idx];
            ((float4*)AVs)[idx] = AVg[idx];
        }
    }

    float acc[4][8];
    #pragma unroll
    for (int i = 0; i < 4; i++)
        #pragma unroll
        for (int c = 0; c < 8; c++) acc[i][c] = 0.f;
    float m_i[4] = {NEG_BIG, NEG_BIG, NEG_BIG, NEG_BIG};
    float l_i[4] = {0.f, 0.f, 0.f, 0.f};
    const float scale = 0.08838834764831843f;   // 1/sqrt(128)

    for (int kb = 0; kb <= qb; kb++) {
        __syncthreads();
        const float* Kblk = Kg + kb*64*HS_;
        const float* Vblk = Vg + kb*64*HS_;
        #pragma unroll
        for (int f = 0; f < 8; f++) {
            int idx = tid + f*256;
            int row = idx >> 5, c4 = (idx & 31) << 2;
            float4 kq = *(const float4*)(Kblk + row*HS_ + c4);
            float4 vq = *(const float4*)(Vblk + row*HS_ + c4);
            Kt[(c4+0)*QT_LD + row] = kq.x; Kt[(c4+1)*QT_LD + row] = kq.y;
            Kt[(c4+2)*QT_LD + row] = kq.z; Kt[(c4+3)*QT_LD + row] = kq.w;
            *(float4*)(Vs + row*HS_ + c4) = vq;
        }
        __syncthreads();

        // S = Q @ K^T (64x64x128), 4x4 per thread
        float s[4][4];
        #pragma unroll
        for (int i = 0; i < 4; i++)
            #pragma unroll
            for (int j = 0; j < 4; j++) s[i][j] = 0.f;
        #pragma unroll 8
        for (int d = 0; d < 128; d++) {
            float4 qv = *(const float4*)(Qt + d*QT_LD + (ty<<2));
            float4 kv = *(const float4*)(Kt + d*QT_LD + (tx<<2));
            s[0][0] += qv.x*kv.x; s[0][1] += qv.x*kv.y; s[0][2] += qv.x*kv.z; s[0][3] += qv.x*kv.w;
            s[1][0] += qv.y*kv.x; s[1][1] += qv.y*kv.y; s[1][2] += qv.y*kv.z; s[1][3] += qv.y*kv.w;
            s[2][0] += qv.z*kv.x; s[2][1] += qv.z*kv.y; s[2][2] += qv.z*kv.z; s[2][3] += qv.z*kv.w;
            s[3][0] += qv.w*kv.x; s[3][1] += qv.w*kv.y; s[3][2] += qv.w*kv.z; s[3][3] += qv.w*kv.w;
        }

        const bool diag = (kb == qb);
        #pragma unroll
        for (int i = 0; i < 4; i++) {
            #pragma unroll
            for (int j = 0; j < 4; j++) {
                float sv = s[i][j] * scale;
                if (diag && ((tx<<2)+j) > ((ty<<2)+i)) sv = NEG_BIG;
                s[i][j] = sv;
            }
            float r = fmaxf(fmaxf(s[i][0], s[i][1]), fmaxf(s[i][2], s[i][3]));
            r = fmaxf(r, __shfl_xor_sync(0xffffffffu, r, 8));
            r = fmaxf(r, __shfl_xor_sync(0xffffffffu, r, 4));
            r = fmaxf(r, __shfl_xor_sync(0xffffffffu, r, 2));
            r = fmaxf(r, __shfl_xor_sync(0xffffffffu, r, 1));
            float mn   = fmaxf(m_i[i], r);
            float corr = __expf(m_i[i] - mn);
            float rs = 0.f;
            #pragma unroll
            for (int j = 0; j < 4; j++) {
                float p = __expf(s[i][j] - mn);
                Ss[((ty<<2)+i)*SS_LD + (tx<<2)+j] = p;
                rs += p;
            }
            rs += __shfl_xor_sync(0xffffffffu, rs, 8);
            rs += __shfl_xor_sync(0xffffffffu, rs, 4);
            rs += __shfl_xor_sync(0xffffffffu, rs, 2);
            rs += __shfl_xor_sync(0xffffffffu, rs, 1);
            l_i[i] = l_i[i]*corr + rs;
            m_i[i] = mn;
            #pragma unroll
            for (int c = 0; c < 8; c++) acc[i][c] *= corr;
        }
        __syncthreads();

        // O += P @ V (64x128x64), rows ty*4..+3, cols tx*8..+7
        #pragma unroll 2
        for (int j = 0; j < 64; j++) {
            float4 v0 = *(const float4*)(Vs + j*HS_ + (tx<<3));
            float4 v1 = *(const float4*)(Vs + j*HS_ + (tx<<3) + 4);
            #pragma unroll
            for (int i = 0; i < 4; i++) {
                float p = Ss[((ty<<2)+i)*SS_LD + j];
                acc[i][0] += p*v0.x; acc[i][1] += p*v0.y; acc[i][2] += p*v0.z; acc[i][3] += p*v0.w;
                acc[i][4] += p*v1.x; acc[i][5] += p*v1.y; acc[i][6] += p*v1.z; acc[i][7] += p*v1.w;
            }
        }
    }

    // ----- adapter attention (q already in Qt) -----
    float sa[4][AL_];
    #pragma unroll
    for (int i = 0; i < 4; i++)
        #pragma unroll
        for (int j = 0; j < AL_; j++) sa[i][j] = 0.f;
    #pragma unroll
    for (int dd = 0; dd < 8; dd++) {
        int d = tx + dd*16;
        float qv[4];
        #pragma unroll
        for (int i = 0; i < 4; i++) qv[i] = Qt[d*QT_LD + (ty<<2) + i];
        #pragma unroll
        for (int j = 0; j < AL_; j++) {
            float a = AKs[j*HS_ + d];
            #pragma unroll
            for (int i = 0; i < 4; i++) sa[i][j] += qv[i]*a;
        }
    }
    #pragma unroll
    for (int i = 0; i < 4; i++)
        #pragma unroll
        for (int j = 0; j < AL_; j++) {
            sa[i][j] += __shfl_xor_sync(0xffffffffu, sa[i][j], 8);
            sa[i][j] += __shfl_xor_sync(0xffffffffu, sa[i][j], 4);
            sa[i][j] += __shfl_xor_sync(0xffffffffu, sa[i][j], 2);
            sa[i][j] += __shfl_xor_sync(0xffffffffu, sa[i][j], 1);
        }

    const float g = gating[h];
    const int b = bh >> 4;
    #pragma unroll
    for (int i = 0; i < 4; i++) {
        const int trow = qb*64 + (ty<<2) + i;
        float mx = sa[i][0]*scale;
        #pragma unroll
        for (int j = 1; j < AL_; j++) mx = fmaxf(mx, sa[i][j]*scale);
        float pa[AL_]; float ssum = 0.f;
        #pragma unroll
        for (int j = 0; j < AL_; j++) { pa[j] = __expf(sa[i][j]*scale - mx); ssum += pa[j]; }
        const float pg = g / ssum;
        const float inv_l = 1.f / l_i[i];
        float o[8];
        #pragma unroll
        for (int c = 0; c < 8; c++) o[c] = acc[i][c]*inv_l;
        #pragma unroll
        for (int j = 0; j < AL_; j++) {
            float p = pa[j]*pg;
            const float* av = AVs + j*HS_ + (tx<<3);
            #pragma unroll
            for (int c = 0; c < 8; c++) o[c] += p*av[c];
        }
        float* dst = g_Y + (b*T_ + trow)*C_ + h*HS_ + (tx<<3);
        *(float4*)dst     = make_float4(o[0], o[1], o[2], o[3]);
        *(float4*)(dst+4) = make_float4(o[4], o[5], o[6], o[7]);
    }
}

// ======================================================================
extern "C" void kernel_launch(void* const* d_in, const int* in_sizes, int n_in,
                              void* d_out, int out_size)
{
    const float* x      = (const float*)d_in[0];
    const float* rope   = (const float*)d_in[1];
    // d_in[2] = mask (causal, implied)
    const float* W_attn = (const float*)d_in[3];
    const float* W_proj = (const float*)d_in[4];
    const float* emb    = (const float*)d_in[5];
    const float* gating = (const float*)d_in[6];
    float* out = (float*)d_out;

    float* Yptr = nullptr;
    cudaGetSymbolAddress((void**)&Yptr, g_Y);

    // 1) QKV GEMM + rope + scatter
    sgemm_nt<0><<<dim3(48, 32), 256>>>(x, W_attn, rope, nullptr);
    // 2) adapter k/v
    adapter_kv<<<4096, 128>>>(W_attn, emb);
    // 3) flash attention + fused adapter attention + gating
    cudaFuncSetAttribute(flash_kernel, cudaFuncAttributeMaxDynamicSharedMemorySize,
                         FLASH_SMEM_BYTES);
    flash_kernel<<<dim3(T_/64, B_*H_), 256, FLASH_SMEM_BYTES>>>(gating);
    // 4) output projection
    sgemm_nt<1><<<dim3(16, 32), 256>>>(Yptr, W_proj, nullptr, out);
}

// round 3
// speedup vs baseline: 1.6085x; 1.6085x over previous
#include <cuda_runtime.h>
#include <cuda_bf16.h>
#include <math.h>
#include <stdint.h>

// Problem constants
#define B_ 2
#define T_ 2048
#define C_ 2048
#define H_ 16
#define HS_ 128
#define AL_ 10
#define KDIM 2048
#define M_ROWS 4096

#define NEG_BIG (-1e30f)

// ---------------- scratch ----------------
__device__ float g_Q[B_*H_*T_*HS_];
__device__ float g_K[B_*H_*T_*HS_];
__device__ float g_V[B_*H_*T_*HS_];
__device__ float g_Y[M_ROWS*C_];
__device__ float g_AK[H_*AL_*HS_];
__device__ float g_AV[H_*AL_*HS_];

// ======================= helpers =======================
__device__ __forceinline__ uint32_t smem_u32(const void* p) {
    uint32_t a;
    asm("{ .reg .u64 t; cvta.to.shared.u64 t, %1; cvt.u32.u64 %0, t; }" : "=r"(a) : "l"(p));
    return a;
}

#define LDSM_X4(r, addr) \
    asm volatile("ldmatrix.sync.aligned.m8n8.x4.shared.b16 {%0,%1,%2,%3}, [%4];" \
        : "=r"((r)[0]), "=r"((r)[1]), "=r"((r)[2]), "=r"((r)[3]) : "r"(addr))

#define MMA_BF16(d, a, b0, b1) \
    asm volatile("mma.sync.aligned.m16n8k16.row.col.f32.bf16.bf16.f32 " \
        "{%0,%1,%2,%3}, {%4,%5,%6,%7}, {%8,%9}, {%0,%1,%2,%3};" \
        : "+f"((d)[0]), "+f"((d)[1]), "+f"((d)[2]), "+f"((d)[3]) \
        : "r"((a)[0]), "r"((a)[1]), "r"((a)[2]), "r"((a)[3]), "r"(b0), "r"(b1))

// swizzled byte offset inside a [128 rows][64B] bf16 tile (4x 16B chunks/row)
__device__ __forceinline__ uint32_t tswz(int row, int chunk) {
    return (uint32_t)(row * 64 + ((chunk ^ ((row >> 1) & 3)) << 4));
}

// convert 8 fp32 -> 8 bf16 hi + 8 bf16 lo (split-bf16)
__device__ __forceinline__ void cvt8(const float* f, uint4& hi, uint4& lo) {
    uint32_t h[4], l[4];
    #pragma unroll
    for (int m = 0; m < 4; m++) {
        float a = f[2*m], b = f[2*m+1];
        __nv_bfloat162 th = __floats2bfloat162_rn(a, b);
        float ra = a - __low2float(th);
        float rb = b - __high2float(th);
        __nv_bfloat162 tl = __floats2bfloat162_rn(ra, rb);
        h[m] = *reinterpret_cast<uint32_t*>(&th);
        l[m] = *reinterpret_cast<uint32_t*>(&tl);
    }
    hi = make_uint4(h[0], h[1], h[2], h[3]);
    lo = make_uint4(l[0], l[1], l[2], l[3]);
}

// ======================================================================
// split-bf16 x3 GEMM (NT): C[m][n] = sum_k A[m][k]*Bw[n][k] via mma.sync.
// CTA tile 128x128, KC=32, 2-stage double buffer, 256 thr (8 warps 2x4).
// MODE 0: rope + scatter to g_Q/g_K/g_V.   MODE 1: plain write to Cout.
// ======================================================================
#define KC 32
#define TILE_B 8192                 // one bf16 tile: 128 x 32 x 2B
#define STAGE_B (4*TILE_B)          // Ahi, Alo, Bhi, Blo
#define GEMM_SMEM (2*STAGE_B)       // 64 KB

template<int MODE>
__global__ __launch_bounds__(256, 1) void tgemm(
    const float* __restrict__ A, const float* __restrict__ Bw,
    const float* __restrict__ rope, float* __restrict__ Cout)
{
    extern __shared__ __align__(1024) char smx[];
    const uint32_t sb = smem_u32(smx);

    const int tid  = threadIdx.x;
    const int wid  = tid >> 5;
    const int lane = tid & 31;
    const int wm   = wid & 1;        // 0..1  (64 rows each)
    const int wn   = wid >> 1;       // 0..3  (32 cols each)
    const int bm   = blockIdx.y << 7;
    const int bn   = blockIdx.x << 7;

    // ---- per-thread load slots: slot f: idx = tid + 256f -> row=idx>>2, chunk=idx&3
    int lrow[2], lchk[2]; uint32_t lsw[2];
    #pragma unroll
    for (int f = 0; f < 2; f++) {
        int idx = tid + (f << 8);
        lrow[f] = idx >> 2; lchk[f] = idx & 3;
        lsw[f] = tswz(lrow[f], lchk[f]);
    }

    // ---- per-thread ldmatrix offsets (within a tile)
    const int grp = lane >> 3, lr = lane & 7;
    uint32_t offA[4][2], offB[2][2];
    #pragma unroll
    for (int i = 0; i < 4; i++)
        #pragma unroll
        for (int ks = 0; ks < 2; ks++) {
            int row = wm*64 + i*16 + (grp & 1)*8 + lr;
            offA[i][ks] = tswz(row, (grp >> 1) + 2*ks);
        }
    #pragma unroll
    for (int jj = 0; jj < 2; jj++)
        #pragma unroll
        for (int ks = 0; ks < 2; ks++) {
            int row = wn*32 + jj*16 + (grp >> 1)*8 + lr;
            offB[jj][ks] = tswz(row, (grp & 1) + 2*ks);
        }

    float acc[4][4][4];
    #pragma unroll
    for (int i = 0; i < 4; i++)
        #pragma unroll
        for (int j = 0; j < 4; j++)
            #pragma unroll
            for (int c = 0; c < 4; c++) acc[i][j][c] = 0.f;

    const float* Ab = A  + (long)bm * KDIM;
    const float* Bb = Bw + (long)bn * KDIM;

    float regA[2][8], regB[2][8];

    // ---- prologue: chunk 0
    #pragma unroll
    for (int f = 0; f < 2; f++) {
        *(float4*)(regA[f])   = *(const float4*)(Ab + (long)lrow[f]*KDIM + lchk[f]*8);
        *(float4*)(regA[f]+4) = *(const float4*)(Ab + (long)lrow[f]*KDIM + lchk[f]*8 + 4);
        *(float4*)(regB[f])   = *(const float4*)(Bb + (long)lrow[f]*KDIM + lchk[f]*8);
        *(float4*)(regB[f]+4) = *(const float4*)(Bb + (long)lrow[f]*KDIM + lchk[f]*8 + 4);
    }
    {
        char* st = smx;   // stage 0
        #pragma unroll
        for (int f = 0; f < 2; f++) {
            uint4 hi, lo;
            cvt8(regA[f], hi, lo);
            *(uint4*)(st + 0*TILE_B + lsw[f]) = hi;
            *(uint4*)(st + 1*TILE_B + lsw[f]) = lo;
            cvt8(regB[f], hi, lo);
            *(uint4*)(st + 2*TILE_B + lsw[f]) = hi;
            *(uint4*)(st + 3*TILE_B + lsw[f]) = lo;
        }
    }
    __syncthreads();

    const int NCH = KDIM / KC;       // 64
    for (int c = 0; c < NCH; c++) {
        // prefetch chunk c+1
        if (c + 1 < NCH) {
            const int kb = (c + 1) * KC;
            #pragma unroll
            for (int f = 0; f < 2; f++) {
                *(float4*)(regA[f])   = *(const float4*)(Ab + (long)lrow[f]*KDIM + kb + lchk[f]*8);
                *(float4*)(regA[f]+4) = *(const float4*)(Ab + (long)lrow[f]*KDIM + kb + lchk[f]*8 + 4);
                *(float4*)(regB[f])   = *(const float4*)(Bb + (long)lrow[f]*KDIM + kb + lchk[f]*8);
                *(float4*)(regB[f]+4) = *(const float4*)(Bb + (long)lrow[f]*KDIM + kb + lchk[f]*8 + 4);
            }
        }

        // mma on stage c&1
        const uint32_t stg = sb + (c & 1) * STAGE_B;
        #pragma unroll
        for (int ks = 0; ks < 2; ks++) {
            uint32_t ah[4][4], al[4][4], bh[2][4], bl[2][4];
            #pragma unroll
            for (int i = 0; i < 4; i++) {
                LDSM_X4(ah[i], stg + 0*TILE_B + offA[i][ks]);
                LDSM_X4(al[i], stg + 1*TILE_B + offA[i][ks]);
            }
            #pragma unroll
            for (int jj = 0; jj < 2; jj++) {
                LDSM_X4(bh[jj], stg + 2*TILE_B + offB[jj][ks]);
                LDSM_X4(bl[jj], stg + 3*TILE_B + offB[jj][ks]);
            }
            #pragma unroll
            for (int i = 0; i < 4; i++)
                #pragma unroll
                for (int j = 0; j < 4; j++) {
                    const int jj = j >> 1, jo = (j & 1) << 1;
                    MMA_BF16(acc[i][j], ah[i], bh[jj][jo], bh[jj][jo+1]);
                    MMA_BF16(acc[i][j], ah[i], bl[jj][jo], bl[jj][jo+1]);
                    MMA_BF16(acc[i][j], al[i], bh[jj][jo], bh[jj][jo+1]);
                }
        }

        // store chunk c+1 into stage (c+1)&1
        if (c + 1 < NCH) {
            char* st = smx + ((c + 1) & 1) * STAGE_B;
            #pragma unroll
            for (int f = 0; f < 2; f++) {
                uint4 hi, lo;
                cvt8(regA[f], hi, lo);
                *(uint4*)(st + 0*TILE_B + lsw[f]) = hi;
                *(uint4*)(st + 1*TILE_B + lsw[f]) = lo;
                cvt8(regB[f], hi, lo);
                *(uint4*)(st + 2*TILE_B + lsw[f]) = hi;
                *(uint4*)(st + 3*TILE_B + lsw[f]) = lo;
            }
        }
        __syncthreads();
    }

    // ---------------- epilogue ----------------
    const int lr4 = lane >> 2;
    const int lc2 = (lane & 3) << 1;

    if (MODE == 0) {
        const int sel = bn >> 11;
        const int hh  = (bn & 2047) >> 7;
        float* base = (sel == 0 ? g_Q : (sel == 1 ? g_K : g_V));
        #pragma unroll
        for (int i = 0; i < 4; i++) {
            #pragma unroll
            for (int j = 0; j < 4; j++) {
                const int d = wn*32 + j*8 + lc2;
                #pragma unroll
                for (int rh = 0; rh < 2; rh++) {
                    const int m = bm + wm*64 + i*16 + lr4 + rh*8;
                    const int b = m >> 11, t = m & 2047;
                    float v0 = acc[i][j][rh*2], v1 = acc[i][j][rh*2+1];
                    if (sel < 2) {
                        const float2 rr = *(const float2*)(rope + (long)t*128 + d);
                        const float o0 = v0*rr.x - v1*rr.y;
                        const float o1 = v1*rr.x + v0*rr.y;
                        v0 = o0; v1 = o1;
                    }
                    *(float2*)(base + ((long)(b*H_ + hh)*T_ + t)*HS_ + d) = make_float2(v0, v1);
                }
            }
        }
    } else {
        #pragma unroll
        for (int i = 0; i < 4; i++)
            #pragma unroll
            for (int j = 0; j < 4; j++) {
                const int ncol = bn + wn*32 + j*8 + lc2;
                #pragma unroll
                for (int rh = 0; rh < 2; rh++) {
                    const int m = bm + wm*64 + i*16 + lr4 + rh*8;
                    *(float2*)(Cout + (long)m*C_ + ncol) =
                        make_float2(acc[i][j][rh*2], acc[i][j][rh*2+1]);
                }
            }
    }
}

// ======================================================================
// Adapter K/V (unchanged)
// ======================================================================
__global__ __launch_bounds__(128) void adapter_kv(
    const float* __restrict__ W, const float* __restrict__ emb)
{
    const int bx = blockIdx.x;
    const int np = 2048 + bx;
    const float* wrow = W + (long)np * KDIM;

    float part[AL_] = {};
    for (int k = threadIdx.x; k < KDIM; k += 128) {
        float w = wrow[k];
        #pragma unroll
        for (int j = 0; j < AL_; j++) part[j] += w * emb[j*KDIM + k];
    }
    #pragma unroll
    for (int j = 0; j < AL_; j++)
        #pragma unroll
        for (int off = 16; off; off >>= 1)
            part[j] += __shfl_xor_sync(0xffffffffu, part[j], off);

    __shared__ float red[AL_][4];
    const int w = threadIdx.x >> 5, lane = threadIdx.x & 31;
    if (lane == 0)
        #pragma unroll
        for (int j = 0; j < AL_; j++) red[j][w] = part[j];
    __syncthreads();
    if (threadIdx.x < AL_) {
        const int j = threadIdx.x;
        float s = red[j][0] + red[j][1] + red[j][2] + red[j][3];
        const int isv = bx >> 11;
        const int nn  = bx & 2047;
        const int h   = nn >> 7, d = nn & 127;
        float* dst = isv ? g_AV : g_AK;
        dst[(h*AL_ + j)*HS_ + d] = s;
    }
}

// ======================================================================
// Flash attention (unchanged; fp32 FFMA)
// ======================================================================
#define QT_LD 68
#define SS_LD 65
#define FLASH_SMEM_FLOATS (128*QT_LD*2 + 64*128 + 64*SS_LD + 2*AL_*HS_)
#define FLASH_SMEM_BYTES  (FLASH_SMEM_FLOATS*4)

__global__ __launch_bounds__(256, 1) void flash_kernel(const float* __restrict__ gating)
{
    extern __shared__ float sm[];
    float* Qt  = sm;
    float* Kt  = Qt  + 128*QT_LD;
    float* Vs  = Kt  + 128*QT_LD;
    float* Ss  = Vs  + 64*128;
    float* AKs = Ss  + 64*SS_LD;
    float* AVs = AKs + AL_*HS_;

    const int tid = threadIdx.x;
    const int tx = tid & 15, ty = tid >> 4;
    const int qb = blockIdx.x;
    const int bh = blockIdx.y;
    const int h  = bh & 15;

    const float* Qg = g_Q + bh*T_*HS_ + qb*64*HS_;
    const float* Kg = g_K + bh*T_*HS_;
    const float* Vg = g_V + bh*T_*HS_;

    #pragma unroll
    for (int f = 0; f < 8; f++) {
        int idx = tid + f*256;
        int row = idx >> 5, c4 = (idx & 31) << 2;
        float4 q = *(const float4*)(Qg + row*HS_ + c4);
        Qt[(c4+0)*QT_LD + row] = q.x; Qt[(c4+1)*QT_LD + row] = q.y;
        Qt[(c4+2)*QT_LD + row] = q.z; Qt[(c4+3)*QT_LD + row] = q.w;
    }
    {
        const float4* AKg = (const float4*)(g_AK + h*AL_*HS_);
        const float4* AVg = (const float4*)(g_AV + h*AL_*HS_);
        for (int idx = tid; idx < AL_*HS_/4; idx += 256) {
            ((float4*)AKs)[idx] = AKg[idx];
            ((float4*)AVs)[idx] = AVg[idx];
        }
    }

    float acc[4][8];
    #pragma unroll
    for (int i = 0; i < 4; i++)
        #pragma unroll
        for (int c = 0; c < 8; c++) acc[i][c] = 0.f;
    float m_i[4] = {NEG_BIG, NEG_BIG, NEG_BIG, NEG_BIG};
    float l_i[4] = {0.f, 0.f, 0.f, 0.f};
    const float scale = 0.08838834764831843f;

    for (int kb = 0; kb <= qb; kb++) {
        __syncthreads();
        const float* Kblk = Kg + kb*64*HS_;
        const float* Vblk = Vg + kb*64*HS_;
        #pragma unroll
        for (int f = 0; f < 8; f++) {
            int idx = tid + f*256;
            int row = idx >> 5, c4 = (idx & 31) << 2;
            float4 kq = *(const float4*)(Kblk + row*HS_ + c4);
            float4 vq = *(const float4*)(Vblk + row*HS_ + c4);
            Kt[(c4+0)*QT_LD + row] = kq.x; Kt[(c4+1)*QT_LD + row] = kq.y;
            Kt[(c4+2)*QT_LD + row] = kq.z; Kt[(c4+3)*QT_LD + row] = kq.w;
            *(float4*)(Vs + row*HS_ + c4) = vq;
        }
        __syncthreads();

        float s[4][4];
        #pragma unroll
        for (int i = 0; i < 4; i++)
            #pragma unroll
            for (int j = 0; j < 4; j++) s[i][j] = 0.f;
        #pragma unroll 8
        for (int d = 0; d < 128; d++) {
            float4 qv = *(const float4*)(Qt + d*QT_LD + (ty<<2));
            float4 kv = *(const float4*)(Kt + d*QT_LD + (tx<<2));
            s[0][0] += qv.x*kv.x; s[0][1] += qv.x*kv.y; s[0][2] += qv.x*kv.z; s[0][3] += qv.x*kv.w;
            s[1][0] += qv.y*kv.x; s[1][1] += qv.y*kv.y; s[1][2] += qv.y*kv.z; s[1][3] += qv.y*kv.w;
            s[2][0] += qv.z*kv.x; s[2][1] += qv.z*kv.y; s[2][2] += qv.z*kv.z; s[2][3] += qv.z*kv.w;
            s[3][0] += qv.w*kv.x; s[3][1] += qv.w*kv.y; s[3][2] += qv.w*kv.z; s[3][3] += qv.w*kv.w;
        }

        const bool diag = (kb == qb);
        #pragma unroll
        for (int i = 0; i < 4; i++) {
            #pragma unroll
            for (int j = 0; j < 4; j++) {
                float sv = s[i][j] * scale;
                if (diag && ((tx<<2)+j) > ((ty<<2)+i)) sv = NEG_BIG;
                s[i][j] = sv;
            }
            float r = fmaxf(fmaxf(s[i][0], s[i][1]), fmaxf(s[i][2], s[i][3]));
            r = fmaxf(r, __shfl_xor_sync(0xffffffffu, r, 8));
            r = fmaxf(r, __shfl_xor_sync(0xffffffffu, r, 4));
            r = fmaxf(r, __shfl_xor_sync(0xffffffffu, r, 2));
            r = fmaxf(r, __shfl_xor_sync(0xffffffffu, r, 1));
            float mn   = fmaxf(m_i[i], r);
            float corr = __expf(m_i[i] - mn);
            float rs = 0.f;
            #pragma unroll
            for (int j = 0; j < 4; j++) {
                float p = __expf(s[i][j] - mn);
                Ss[((ty<<2)+i)*SS_LD + (tx<<2)+j] = p;
                rs += p;
            }
            rs += __shfl_xor_sync(0xffffffffu, rs, 8);
            rs += __shfl_xor_sync(0xffffffffu, rs, 4);
            rs += __shfl_xor_sync(0xffffffffu, rs, 2);
            rs += __shfl_xor_sync(0xffffffffu, rs, 1);
            l_i[i] = l_i[i]*corr + rs;
            m_i[i] = mn;
            #pragma unroll
            for (int c = 0; c < 8; c++) acc[i][c] *= corr;
        }
        __syncthreads();

        #pragma unroll 2
        for (int j = 0; j < 64; j++) {
            float4 v0 = *(const float4*)(Vs + j*HS_ + (tx<<3));
            float4 v1 = *(const float4*)(Vs + j*HS_ + (tx<<3) + 4);
            #pragma unroll
            for (int i = 0; i < 4; i++) {
                float p = Ss[((ty<<2)+i)*SS_LD + j];
                acc[i][0] += p*v0.x; acc[i][1] += p*v0.y; acc[i][2] += p*v0.z; acc[i][3] += p*v0.w;
                acc[i][4] += p*v1.x; acc[i][5] += p*v1.y; acc[i][6] += p*v1.z; acc[i][7] += p*v1.w;
            }
        }
    }

    float sa[4][AL_];
    #pragma unroll
    for (int i = 0; i < 4; i++)
        #pragma unroll
        for (int j = 0; j < AL_; j++) sa[i][j] = 0.f;
    #pragma unroll
    for (int dd = 0; dd < 8; dd++) {
        int d = tx + dd*16;
        float qv[4];
        #pragma unroll
        for (int i = 0; i < 4; i++) qv[i] = Qt[d*QT_LD + (ty<<2) + i];
        #pragma unroll
        for (int j = 0; j < AL_; j++) {
            float a = AKs[j*HS_ + d];
            #pragma unroll
            for (int i = 0; i < 4; i++) sa[i][j] += qv[i]*a;
        }
    }
    #pragma unroll
    for (int i = 0; i < 4; i++)
        #pragma unroll
        for (int j = 0; j < AL_; j++) {
            sa[i][j] += __shfl_xor_sync(0xffffffffu, sa[i][j], 8);
            sa[i][j] += __shfl_xor_sync(0xffffffffu, sa[i][j], 4);
            sa[i][j] += __shfl_xor_sync(0xffffffffu, sa[i][j], 2);
            sa[i][j] += __shfl_xor_sync(0xffffffffu, sa[i][j], 1);
        }

    const float g = gating[h];
    const int b = bh >> 4;
    #pragma unroll
    for (int i = 0; i < 4; i++) {
        const int trow = qb*64 + (ty<<2) + i;
        float mx = sa[i][0]*scale;
        #pragma unroll
        for (int j = 1; j < AL_; j++) mx = fmaxf(mx, sa[i][j]*scale);
        float pa[AL_]; float ssum = 0.f;
        #pragma unroll
        for (int j = 0; j < AL_; j++) { pa[j] = __expf(sa[i][j]*scale - mx); ssum += pa[j]; }
        const float pg = g / ssum;
        const float inv_l = 1.f / l_i[i];
        float o[8];
        #pragma unroll
        for (int c = 0; c < 8; c++) o[c] = acc[i][c]*inv_l;
        #pragma unroll
        for (int j = 0; j < AL_; j++) {
            float p = pa[j]*pg;
            const float* av = AVs + j*HS_ + (tx<<3);
            #pragma unroll
            for (int c = 0; c < 8; c++) o[c] += p*av[c];
        }
        float* dst = g_Y + (b*T_ + trow)*C_ + h*HS_ + (tx<<3);
        *(float4*)dst     = make_float4(o[0], o[1], o[2], o[3]);
        *(float4*)(dst+4) = make_float4(o[4], o[5], o[6], o[7]);
    }
}

// ======================================================================
extern "C" void kernel_launch(void* const* d_in, const int* in_sizes, int n_in,
                              void* d_out, int out_size)
{
    const float* x      = (const float*)d_in[0];
    const float* rope   = (const float*)d_in[1];
    const float* W_attn = (const float*)d_in[3];
    const float* W_proj = (const float*)d_in[4];
    const float* emb    = (const float*)d_in[5];
    const float* gating = (const float*)d_in[6];
    float* out = (float*)d_out;

    float* Yptr = nullptr;
    cudaGetSymbolAddress((void**)&Yptr, g_Y);

    cudaFuncSetAttribute(tgemm<0>, cudaFuncAttributeMaxDynamicSharedMemorySize, GEMM_SMEM);
    cudaFuncSetAttribute(tgemm<1>, cudaFuncAttributeMaxDynamicSharedMemorySize, GEMM_SMEM);
    cudaFuncSetAttribute(flash_kernel, cudaFuncAttributeMaxDynamicSharedMemorySize, FLASH_SMEM_BYTES);

    // 1) QKV GEMM (split-bf16 mma.sync) + rope + scatter
    tgemm<0><<<dim3(48, 32), 256, GEMM_SMEM>>>(x, W_attn, rope, nullptr);
    // 2) adapter k/v
    adapter_kv<<<4096, 128>>>(W_attn, emb);
    // 3) flash attention + fused adapter attention + gating
    flash_kernel<<<dim3(T_/64, B_*H_), 256, FLASH_SMEM_BYTES>>>(gating);
    // 4) output projection (split-bf16 mma.sync)
    tgemm<1><<<dim3(16, 32), 256, GEMM_SMEM>>>(Yptr, W_proj, nullptr, out);
}

// round 4
// speedup vs baseline: 2.6956x; 1.6759x over previous
#include <cuda_runtime.h>
#include <cuda_bf16.h>
#include <math.h>
#include <stdint.h>

// Problem constants
#define B_ 2
#define T_ 2048
#define C_ 2048
#define H_ 16
#define HS_ 128
#define AL_ 10
#define KDIM 2048
#define M_ROWS 4096

#define NEG_BIG (-1e30f)

// ---------------- scratch ----------------
__device__ float g_Q[B_*H_*T_*HS_];
__device__ float g_K[B_*H_*T_*HS_];
__device__ float g_V[B_*H_*T_*HS_];
__device__ float g_Y[M_ROWS*C_];
__device__ float g_AK[H_*AL_*HS_];
__device__ float g_AV[H_*AL_*HS_];

// ======================= helpers =======================
__device__ __forceinline__ uint32_t smem_u32(const void* p) {
    uint32_t a;
    asm("{ .reg .u64 t; cvta.to.shared.u64 t, %1; cvt.u32.u64 %0, t; }" : "=r"(a) : "l"(p));
    return a;
}

#define LDSM_X4(r, addr) \
    asm volatile("ldmatrix.sync.aligned.m8n8.x4.shared.b16 {%0,%1,%2,%3}, [%4];" \
        : "=r"((r)[0]), "=r"((r)[1]), "=r"((r)[2]), "=r"((r)[3]) : "r"(addr))

#define LDSM_X4_T(r, addr) \
    asm volatile("ldmatrix.sync.aligned.m8n8.x4.trans.shared.b16 {%0,%1,%2,%3}, [%4];" \
        : "=r"((r)[0]), "=r"((r)[1]), "=r"((r)[2]), "=r"((r)[3]) : "r"(addr))

#define MMA_BF16(d, a, b0, b1) \
    asm volatile("mma.sync.aligned.m16n8k16.row.col.f32.bf16.bf16.f32 " \
        "{%0,%1,%2,%3}, {%4,%5,%6,%7}, {%8,%9}, {%0,%1,%2,%3};" \
        : "+f"((d)[0]), "+f"((d)[1]), "+f"((d)[2]), "+f"((d)[3]) \
        : "r"((a)[0]), "r"((a)[1]), "r"((a)[2]), "r"((a)[3]), "r"(b0), "r"(b1))

// swizzled byte offset inside a [rows][64B] bf16 tile (4x 16B chunks/row)
__device__ __forceinline__ uint32_t tswz(int row, int chunk) {
    return (uint32_t)(row * 64 + ((chunk ^ ((row >> 1) & 3)) << 4));
}

// convert 8 fp32 -> 8 bf16 hi + 8 bf16 lo (split-bf16)
__device__ __forceinline__ void cvt8(const float* f, uint4& hi, uint4& lo) {
    uint32_t h[4], l[4];
    #pragma unroll
    for (int m = 0; m < 4; m++) {
        float a = f[2*m], b = f[2*m+1];
        __nv_bfloat162 th = __floats2bfloat162_rn(a, b);
        float ra = a - __low2float(th);
        float rb = b - __high2float(th);
        __nv_bfloat162 tl = __floats2bfloat162_rn(ra, rb);
        h[m] = *reinterpret_cast<uint32_t*>(&th);
        l[m] = *reinterpret_cast<uint32_t*>(&tl);
    }
    hi = make_uint4(h[0], h[1], h[2], h[3]);
    lo = make_uint4(l[0], l[1], l[2], l[3]);
}

__device__ __forceinline__ void pack2(float a, float b, uint32_t& hi, uint32_t& lo) {
    __nv_bfloat162 th = __floats2bfloat162_rn(a, b);
    __nv_bfloat162 tl = __floats2bfloat162_rn(a - __low2float(th), b - __high2float(th));
    hi = *reinterpret_cast<uint32_t*>(&th);
    lo = *reinterpret_cast<uint32_t*>(&tl);
}

// ======================================================================
// split-bf16 x3 GEMM (NT)  (unchanged from round 3)
// ======================================================================
#define KC 32
#define TILE_B 8192
#define STAGE_B (4*TILE_B)
#define GEMM_SMEM (2*STAGE_B)

template<int MODE>
__global__ __launch_bounds__(256, 1) void tgemm(
    const float* __restrict__ A, const float* __restrict__ Bw,
    const float* __restrict__ rope, float* __restrict__ Cout)
{
    extern __shared__ __align__(1024) char smx[];
    const uint32_t sb = smem_u32(smx);

    const int tid  = threadIdx.x;
    const int wid  = tid >> 5;
    const int lane = tid & 31;
    const int wm   = wid & 1;
    const int wn   = wid >> 1;
    const int bm   = blockIdx.y << 7;
    const int bn   = blockIdx.x << 7;

    int lrow[2], lchk[2]; uint32_t lsw[2];
    #pragma unroll
    for (int f = 0; f < 2; f++) {
        int idx = tid + (f << 8);
        lrow[f] = idx >> 2; lchk[f] = idx & 3;
        lsw[f] = tswz(lrow[f], lchk[f]);
    }

    const int grp = lane >> 3, lr = lane & 7;
    uint32_t offA[4][2], offB[2][2];
    #pragma unroll
    for (int i = 0; i < 4; i++)
        #pragma unroll
        for (int ks = 0; ks < 2; ks++) {
            int row = wm*64 + i*16 + (grp & 1)*8 + lr;
            offA[i][ks] = tswz(row, (grp >> 1) + 2*ks);
        }
    #pragma unroll
    for (int jj = 0; jj < 2; jj++)
        #pragma unroll
        for (int ks = 0; ks < 2; ks++) {
            int row = wn*32 + jj*16 + (grp >> 1)*8 + lr;
            offB[jj][ks] = tswz(row, (grp & 1) + 2*ks);
        }

    float acc[4][4][4];
    #pragma unroll
    for (int i = 0; i < 4; i++)
        #pragma unroll
        for (int j = 0; j < 4; j++)
            #pragma unroll
            for (int c = 0; c < 4; c++) acc[i][j][c] = 0.f;

    const float* Ab = A  + (long)bm * KDIM;
    const float* Bb = Bw + (long)bn * KDIM;

    float regA[2][8], regB[2][8];

    #pragma unroll
    for (int f = 0; f < 2; f++) {
        *(float4*)(regA[f])   = *(const float4*)(Ab + (long)lrow[f]*KDIM + lchk[f]*8);
        *(float4*)(regA[f]+4) = *(const float4*)(Ab + (long)lrow[f]*KDIM + lchk[f]*8 + 4);
        *(float4*)(regB[f])   = *(const float4*)(Bb + (long)lrow[f]*KDIM + lchk[f]*8);
        *(float4*)(regB[f]+4) = *(const float4*)(Bb + (long)lrow[f]*KDIM + lchk[f]*8 + 4);
    }
    {
        char* st = smx;
        #pragma unroll
        for (int f = 0; f < 2; f++) {
            uint4 hi, lo;
            cvt8(regA[f], hi, lo);
            *(uint4*)(st + 0*TILE_B + lsw[f]) = hi;
            *(uint4*)(st + 1*TILE_B + lsw[f]) = lo;
            cvt8(regB[f], hi, lo);
            *(uint4*)(st + 2*TILE_B + lsw[f]) = hi;
            *(uint4*)(st + 3*TILE_B + lsw[f]) = lo;
        }
    }
    __syncthreads();

    const int NCH = KDIM / KC;
    for (int c = 0; c < NCH; c++) {
        if (c + 1 < NCH) {
            const int kb = (c + 1) * KC;
            #pragma unroll
            for (int f = 0; f < 2; f++) {
                *(float4*)(regA[f])   = *(const float4*)(Ab + (long)lrow[f]*KDIM + kb + lchk[f]*8);
                *(float4*)(regA[f]+4) = *(const float4*)(Ab + (long)lrow[f]*KDIM + kb + lchk[f]*8 + 4);
                *(float4*)(regB[f])   = *(const float4*)(Bb + (long)lrow[f]*KDIM + kb + lchk[f]*8);
                *(float4*)(regB[f]+4) = *(const float4*)(Bb + (long)lrow[f]*KDIM + kb + lchk[f]*8 + 4);
            }
        }

        const uint32_t stg = sb + (c & 1) * STAGE_B;
        #pragma unroll
        for (int ks = 0; ks < 2; ks++) {
            uint32_t ah[4][4], al[4][4], bh[2][4], bl[2][4];
            #pragma unroll
            for (int i = 0; i < 4; i++) {
                LDSM_X4(ah[i], stg + 0*TILE_B + offA[i][ks]);
                LDSM_X4(al[i], stg + 1*TILE_B + offA[i][ks]);
            }
            #pragma unroll
            for (int jj = 0; jj < 2; jj++) {
                LDSM_X4(bh[jj], stg + 2*TILE_B + offB[jj][ks]);
                LDSM_X4(bl[jj], stg + 3*TILE_B + offB[jj][ks]);
            }
            #pragma unroll
            for (int i = 0; i < 4; i++)
                #pragma unroll
                for (int j = 0; j < 4; j++) {
                    const int jj = j >> 1, jo = (j & 1) << 1;
                    MMA_BF16(acc[i][j], ah[i], bh[jj][jo], bh[jj][jo+1]);
                    MMA_BF16(acc[i][j], ah[i], bl[jj][jo], bl[jj][jo+1]);
                    MMA_BF16(acc[i][j], al[i], bh[jj][jo], bh[jj][jo+1]);
                }
        }

        if (c + 1 < NCH) {
            char* st = smx + ((c + 1) & 1) * STAGE_B;
            #pragma unroll
            for (int f = 0; f < 2; f++) {
                uint4 hi, lo;
                cvt8(regA[f], hi, lo);
                *(uint4*)(st + 0*TILE_B + lsw[f]) = hi;
                *(uint4*)(st + 1*TILE_B + lsw[f]) = lo;
                cvt8(regB[f], hi, lo);
                *(uint4*)(st + 2*TILE_B + lsw[f]) = hi;
                *(uint4*)(st + 3*TILE_B + lsw[f]) = lo;
            }
        }
        __syncthreads();
    }

    const int lr4 = lane >> 2;
    const int lc2 = (lane & 3) << 1;

    if (MODE == 0) {
        const int sel = bn >> 11;
        const int hh  = (bn & 2047) >> 7;
        float* base = (sel == 0 ? g_Q : (sel == 1 ? g_K : g_V));
        #pragma unroll
        for (int i = 0; i < 4; i++) {
            #pragma unroll
            for (int j = 0; j < 4; j++) {
                const int d = wn*32 + j*8 + lc2;
                #pragma unroll
                for (int rh = 0; rh < 2; rh++) {
                    const int m = bm + wm*64 + i*16 + lr4 + rh*8;
                    const int b = m >> 11, t = m & 2047;
                    float v0 = acc[i][j][rh*2], v1 = acc[i][j][rh*2+1];
                    if (sel < 2) {
                        const float2 rr = *(const float2*)(rope + (long)t*128 + d);
                        const float o0 = v0*rr.x - v1*rr.y;
                        const float o1 = v1*rr.x + v0*rr.y;
                        v0 = o0; v1 = o1;
                    }
                    *(float2*)(base + ((long)(b*H_ + hh)*T_ + t)*HS_ + d) = make_float2(v0, v1);
                }
            }
        }
    } else {
        #pragma unroll
        for (int i = 0; i < 4; i++)
            #pragma unroll
            for (int j = 0; j < 4; j++) {
                const int ncol = bn + wn*32 + j*8 + lc2;
                #pragma unroll
                for (int rh = 0; rh < 2; rh++) {
                    const int m = bm + wm*64 + i*16 + lr4 + rh*8;
                    *(float2*)(Cout + (long)m*C_ + ncol) =
                        make_float2(acc[i][j][rh*2], acc[i][j][rh*2+1]);
                }
            }
    }
}

// ======================================================================
// Adapter K/V (unchanged)
// ======================================================================
__global__ __launch_bounds__(128) void adapter_kv(
    const float* __restrict__ W, const float* __restrict__ emb)
{
    const int bx = blockIdx.x;
    const int np = 2048 + bx;
    const float* wrow = W + (long)np * KDIM;

    float part[AL_] = {};
    for (int k = threadIdx.x; k < KDIM; k += 128) {
        float w = wrow[k];
        #pragma unroll
        for (int j = 0; j < AL_; j++) part[j] += w * emb[j*KDIM + k];
    }
    #pragma unroll
    for (int j = 0; j < AL_; j++)
        #pragma unroll
        for (int off = 16; off; off >>= 1)
            part[j] += __shfl_xor_sync(0xffffffffu, part[j], off);

    __shared__ float red[AL_][4];
    const int w = threadIdx.x >> 5, lane = threadIdx.x & 31;
    if (lane == 0)
        #pragma unroll
        for (int j = 0; j < AL_; j++) red[j][w] = part[j];
    __syncthreads();
    if (threadIdx.x < AL_) {
        const int j = threadIdx.x;
        float s = red[j][0] + red[j][1] + red[j][2] + red[j][3];
        const int isv = bx >> 11;
        const int nn  = bx & 2047;
        const int h   = nn >> 7, d = nn & 127;
        float* dst = isv ? g_AV : g_AK;
        dst[(h*AL_ + j)*HS_ + d] = s;
    }
}

// ======================================================================
// Flash attention on tensor cores (split-bf16 x3) + fused adapter/gating.
// BM=128, BN=64, 8 warps (one per 16 q-rows). Q resident in smem hi/lo.
// ======================================================================
#define FQHI 0
#define FQLO 32768
#define FKHI 65536
#define FKLO 81920
#define FVHI 98304
#define FVLO 114688
#define FAK  131072
#define FAV  136192
#define FLASH_SMEM 141312

__global__ __launch_bounds__(256, 1) void flash_mma(const float* __restrict__ gating)
{
    extern __shared__ __align__(1024) char fsm[];
    const uint32_t sb = smem_u32(fsm);

    const int tid  = threadIdx.x;
    const int w    = tid >> 5;
    const int lane = tid & 31;
    const int grp  = lane >> 3, lr = lane & 7;
    const int lam  = lane & 3;          // lambda
    const int rsub = lane >> 2;         // 0..7

    const int qb = (gridDim.x - 1) - blockIdx.x;   // heavy blocks first
    const int bhI = blockIdx.y;
    const int h  = bhI & 15;
    const int b  = bhI >> 4;

    const float* Qg = g_Q + (long)bhI*T_*HS_ + (long)qb*128*HS_;
    const float* Kg = g_K + (long)bhI*T_*HS_;
    const float* Vg = g_V + (long)bhI*T_*HS_;

    // ---- load Q (128x128 fp32) -> bf16 hi/lo swizzled tiles ----
    #pragma unroll
    for (int f = 0; f < 8; f++) {
        const int slot = tid + (f << 8);          // 0..2047
        const int row = slot >> 4, c8 = slot & 15;
        float v[8];
        *(float4*)(v)   = *(const float4*)(Qg + (long)row*HS_ + c8*8);
        *(float4*)(v+4) = *(const float4*)(Qg + (long)row*HS_ + c8*8 + 4);
        uint4 hi, lo; cvt8(v, hi, lo);
        const uint32_t off = (uint32_t)((c8 >> 2) * 8192) + tswz(row, c8 & 3);
        *(uint4*)(fsm + FQHI + off) = hi;
        *(uint4*)(fsm + FQLO + off) = lo;
    }
    // ---- adapter tiles (fp32) ----
    {
        const float4* AKg = (const float4*)(g_AK + h*AL_*HS_);
        const float4* AVg = (const float4*)(g_AV + h*AL_*HS_);
        for (int i = tid; i < AL_*HS_/4; i += 256) {
            ((float4*)(fsm + FAK))[i] = AKg[i];
            ((float4*)(fsm + FAV))[i] = AVg[i];
        }
    }

    // per-thread state: 2 rows (rsub, rsub+8) within warp's 16 rows
    float O[16][4];
    #pragma unroll
    for (int nf = 0; nf < 16; nf++)
        #pragma unroll
        for (int c = 0; c < 4; c++) O[nf][c] = 0.f;
    float m0 = NEG_BIG, m1 = NEG_BIG, l0 = 0.f, l1 = 0.f;
    const float scale = 0.08838834764831843f;

    const int rowg0 = qb*128 + 16*w + rsub;     // thread's row 0 (global)
    const int warp_rmax = qb*128 + 16*w + 15;

    const int kmax = 2*qb + 2;
    for (int kb = 0; kb < kmax; kb++) {
        __syncthreads();
        // ---- load K/V (64x128 fp32 each) -> bf16 hi/lo ----
        const float* Kblk = Kg + (long)kb*64*HS_;
        const float* Vblk = Vg + (long)kb*64*HS_;
        #pragma unroll
        for (int f = 0; f < 4; f++) {
            const int slot = tid + (f << 8);      // 0..1023
            const int row = slot >> 4, c8 = slot & 15;
            const uint32_t off = (uint32_t)((c8 >> 2) * 4096) + tswz(row, c8 & 3);
            float v[8];
            *(float4*)(v)   = *(const float4*)(Kblk + (long)row*HS_ + c8*8);
            *(float4*)(v+4) = *(const float4*)(Kblk + (long)row*HS_ + c8*8 + 4);
            uint4 hi, lo; cvt8(v, hi, lo);
            *(uint4*)(fsm + FKHI + off) = hi;
            *(uint4*)(fsm + FKLO + off) = lo;
            *(float4*)(v)   = *(const float4*)(Vblk + (long)row*HS_ + c8*8);
            *(float4*)(v+4) = *(const float4*)(Vblk + (long)row*HS_ + c8*8 + 4);
            cvt8(v, hi, lo);
            *(uint4*)(fsm + FVHI + off) = hi;
            *(uint4*)(fsm + FVLO + off) = lo;
        }
        __syncthreads();

        if (kb*64 > warp_rmax) continue;          // fully masked for this warp

        // ---- S = Q K^T (16x64x128 per warp, 3-term split) ----
        float S[8][4];
        #pragma unroll
        for (int j = 0; j < 8; j++)
            #pragma unroll
            for (int c = 0; c < 4; c++) S[j][c] = 0.f;

        #pragma unroll
        for (int ks = 0; ks < 8; ks++) {
            const int tQ = ks >> 1, chb = (ks & 1) << 1;
            const int arow = 16*w + (grp & 1)*8 + lr;
            const uint32_t aoff = (uint32_t)(tQ*8192) + tswz(arow, chb + (grp >> 1));
            uint32_t ah[4], al[4];
            LDSM_X4(ah, sb + FQHI + aoff);
            LDSM_X4(al, sb + FQLO + aoff);
            #pragma unroll
            for (int jj = 0; jj < 4; jj++) {
                const int brow = jj*16 + (grp >> 1)*8 + lr;
                const uint32_t boff = (uint32_t)(tQ*4096) + tswz(brow, (grp & 1) + chb);
                uint32_t kh[4], kl[4];
                LDSM_X4(kh, sb + FKHI + boff);
                LDSM_X4(kl, sb + FKLO + boff);
                #pragma unroll
                for (int j2 = 0; j2 < 2; j2++) {
                    const int j = jj*2 + j2, jo = j2 << 1;
                    MMA_BF16(S[j], ah, kh[jo], kh[jo+1]);
                    MMA_BF16(S[j], ah, kl[jo], kl[jo+1]);
                    MMA_BF16(S[j], al, kh[jo], kh[jo+1]);
                }
            }
        }

        // ---- scale + mask ----
        const bool needMask = (kb*64 + 63) > (qb*128 + 16*w);
        #pragma unroll
        for (int j = 0; j < 8; j++)
            #pragma unroll
            for (int c = 0; c < 4; c++) {
                float sv = S[j][c] * scale;
                if (needMask) {
                    const int colg = kb*64 + j*8 + 2*lam + (c & 1);
                    const int rowg = rowg0 + ((c >> 1) << 3);
                    if (colg > rowg) sv = NEG_BIG;
                }
                S[j][c] = sv;
            }

        // ---- online softmax (rows rsub, rsub+8) ----
        float mx0 = S[0][0], mx1 = S[0][2];
        #pragma unroll
        for (int j = 0; j < 8; j++) {
            mx0 = fmaxf(mx0, fmaxf(S[j][0], S[j][1]));
            mx1 = fmaxf(mx1, fmaxf(S[j][2], S[j][3]));
        }
        mx0 = fmaxf(mx0, __shfl_xor_sync(0xffffffffu, mx0, 1));
        mx0 = fmaxf(mx0, __shfl_xor_sync(0xffffffffu, mx0, 2));
        mx1 = fmaxf(mx1, __shfl_xor_sync(0xffffffffu, mx1, 1));
        mx1 = fmaxf(mx1, __shfl_xor_sync(0xffffffffu, mx1, 2));
        const float mn0 = fmaxf(m0, mx0);
        const float mn1 = fmaxf(m1, mx1);
        const float corr0 = __expf(m0 - mn0);
        const float corr1 = __expf(m1 - mn1);
        float rs0 = 0.f, rs1 = 0.f;
        #pragma unroll
        for (int j = 0; j < 8; j++) {
            S[j][0] = __expf(S[j][0] - mn0);
            S[j][1] = __expf(S[j][1] - mn0);
            S[j][2] = __expf(S[j][2] - mn1);
            S[j][3] = __expf(S[j][3] - mn1);
            rs0 += S[j][0] + S[j][1];
            rs1 += S[j][2] + S[j][3];
        }
        l0 = l0*corr0 + rs0;
        l1 = l1*corr1 + rs1;
        m0 = mn0; m1 = mn1;
        #pragma unroll
        for (int nf = 0; nf < 16; nf++) {
            O[nf][0] *= corr0; O[nf][1] *= corr0;
            O[nf][2] *= corr1; O[nf][3] *= corr1;
        }

        // ---- O += P V (3-term split; P repacked in registers) ----
        #pragma unroll
        for (int ks2 = 0; ks2 < 4; ks2++) {
            const int j0 = 2*ks2, j1 = j0 + 1;
            uint32_t phi[4], plo[4];
            pack2(S[j0][0], S[j0][1], phi[0], plo[0]);
            pack2(S[j0][2], S[j0][3], phi[1], plo[1]);
            pack2(S[j1][0], S[j1][1], phi[2], plo[2]);
            pack2(S[j1][2], S[j1][3], phi[3], plo[3]);
            #pragma unroll
            for (int nc = 0; nc < 8; nc++) {
                const int vrow = ks2*16 + (grp & 1)*8 + lr;
                const uint32_t voff = (uint32_t)((nc >> 1) * 4096)
                                    + tswz(vrow, ((nc & 1) << 1) + (grp >> 1));
                uint32_t vh[4], vl[4];
                LDSM_X4_T(vh, sb + FVHI + voff);
                LDSM_X4_T(vl, sb + FVLO + voff);
                MMA_BF16(O[2*nc],   phi, vh[0], vh[1]);
                MMA_BF16(O[2*nc+1], phi, vh[2], vh[3]);
                MMA_BF16(O[2*nc],   phi, vl[0], vl[1]);
                MMA_BF16(O[2*nc+1], phi, vl[2], vl[3]);
                MMA_BF16(O[2*nc],   plo, vh[0], vh[1]);
                MMA_BF16(O[2*nc+1], plo, vh[2], vh[3]);
            }
        }
    }

    // ---- finalize l across lambda lanes ----
    l0 += __shfl_xor_sync(0xffffffffu, l0, 1);
    l0 += __shfl_xor_sync(0xffffffffu, l0, 2);
    l1 += __shfl_xor_sync(0xffffffffu, l1, 1);
    l1 += __shfl_xor_sync(0xffffffffu, l1, 2);

    // ---- adapter attention (q = hi+lo from smem) ----
    float sa0[AL_], sa1[AL_];
    #pragma unroll
    for (int j = 0; j < AL_; j++) { sa0[j] = 0.f; sa1[j] = 0.f; }
    const float* AKs = (const float*)(fsm + FAK);
    const float* AVs = (const float*)(fsm + FAV);
    #pragma unroll
    for (int rr = 0; rr < 2; rr++) {
        const int rowL = 16*w + rsub + rr*8;
        float* sa = rr ? sa1 : sa0;
        #pragma unroll
        for (int ch = 0; ch < 4; ch++) {
            const uint32_t off = (uint32_t)(lam * 8192) + tswz(rowL, ch);
            uint4 qh = *(const uint4*)(fsm + FQHI + off);
            uint4 ql = *(const uint4*)(fsm + FQLO + off);
            const uint32_t* qhp = (const uint32_t*)&qh;
            const uint32_t* qlp = (const uint32_t*)&ql;
            float q[8];
            #pragma unroll
            for (int e = 0; e < 4; e++) {
                __nv_bfloat162 bh2 = *reinterpret_cast<const __nv_bfloat162*>(&qhp[e]);
                __nv_bfloat162 bl2 = *reinterpret_cast<const __nv_bfloat162*>(&qlp[e]);
                q[2*e]   = __low2float(bh2)  + __low2float(bl2);
                q[2*e+1] = __high2float(bh2) + __high2float(bl2);
            }
            const int d0 = lam*32 + ch*8;
            #pragma unroll
            for (int j = 0; j < AL_; j++) {
                const float* ak = AKs + j*HS_ + d0;
                #pragma unroll
                for (int e = 0; e < 8; e++) sa[j] += q[e] * ak[e];
            }
        }
    }
    #pragma unroll
    for (int j = 0; j < AL_; j++) {
        sa0[j] += __shfl_xor_sync(0xffffffffu, sa0[j], 1);
        sa0[j] += __shfl_xor_sync(0xffffffffu, sa0[j], 2);
        sa1[j] += __shfl_xor_sync(0xffffffffu, sa1[j], 1);
        sa1[j] += __shfl_xor_sync(0xffffffffu, sa1[j], 2);
    }

    const float g = gating[h];
    #pragma unroll
    for (int rr = 0; rr < 2; rr++) {
        float* sa = rr ? sa1 : sa0;
        const float li = rr ? l1 : l0;
        const int rowg = rowg0 + rr*8;
        float mx = sa[0]*scale;
        #pragma unroll
        for (int j = 1; j < AL_; j++) mx = fmaxf(mx, sa[j]*scale);
        float pa[AL_], ssum = 0.f;
        #pragma unroll
        for (int j = 0; j < AL_; j++) { pa[j] = __expf(sa[j]*scale - mx); ssum += pa[j]; }
        const float pg = g / ssum;
        const float inv_l = 1.f / li;
        float* dst = g_Y + ((long)b*T_ + rowg)*C_ + h*HS_;
        #pragma unroll
        for (int nf = 0; nf < 16; nf++) {
            const int d = nf*8 + 2*lam;
            float o0 = O[nf][rr*2]   * inv_l;
            float o1 = O[nf][rr*2+1] * inv_l;
            #pragma unroll
            for (int j = 0; j < AL_; j++) {
                const float p = pa[j] * pg;
                o0 += p * AVs[j*HS_ + d];
                o1 += p * AVs[j*HS_ + d + 1];
            }
            *(float2*)(dst + d) = make_float2(o0, o1);
        }
    }
}

// ======================================================================
extern "C" void kernel_launch(void* const* d_in, const int* in_sizes, int n_in,
                              void* d_out, int out_size)
{
    const float* x      = (const float*)d_in[0];
    const float* rope   = (const float*)d_in[1];
    const float* W_attn = (const float*)d_in[3];
    const float* W_proj = (const float*)d_in[4];
    const float* emb    = (const float*)d_in[5];
    const float* gating = (const float*)d_in[6];
    float* out = (float*)d_out;

    float* Yptr = nullptr;
    cudaGetSymbolAddress((void**)&Yptr, g_Y);

    cudaFuncSetAttribute(tgemm<0>, cudaFuncAttributeMaxDynamicSharedMemorySize, GEMM_SMEM);
    cudaFuncSetAttribute(tgemm<1>, cudaFuncAttributeMaxDynamicSharedMemorySize, GEMM_SMEM);
    cudaFuncSetAttribute(flash_mma, cudaFuncAttributeMaxDynamicSharedMemorySize, FLASH_SMEM);

    // 1) QKV GEMM (split-bf16 mma.sync) + rope + scatter
    tgemm<0><<<dim3(48, 32), 256, GEMM_SMEM>>>(x, W_attn, rope, nullptr);
    // 2) adapter k/v
    adapter_kv<<<4096, 128>>>(W_attn, emb);
    // 3) flash attention on tensor cores + fused adapter/gating
    flash_mma<<<dim3(T_/128, B_*H_), 256, FLASH_SMEM>>>(gating);
    // 4) output projection (split-bf16 mma.sync)
    tgemm<1><<<dim3(16, 32), 256, GEMM_SMEM>>>(Yptr, W_proj, nullptr, out);
}

// round 5
// speedup vs baseline: 2.9193x; 1.0830x over previous
#include <cuda_runtime.h>
#include <cuda_bf16.h>
#include <math.h>
#include <stdint.h>

// Problem constants
#define B_ 2
#define T_ 2048
#define C_ 2048
#define H_ 16
#define HS_ 128
#define AL_ 10
#define KDIM 2048
#define M_ROWS 4096

#define NEG_BIG (-1e30f)

// ---------------- scratch: split-bf16 tensors ----------------
#define QKV_ELEMS (B_*H_*T_*HS_)
__device__ __nv_bfloat16 g_Qh[QKV_ELEMS], g_Ql[QKV_ELEMS];
__device__ __nv_bfloat16 g_Kh[QKV_ELEMS], g_Kl[QKV_ELEMS];
__device__ __nv_bfloat16 g_Vh[QKV_ELEMS], g_Vl[QKV_ELEMS];
__device__ __nv_bfloat16 g_Yh[M_ROWS*C_], g_Yl[M_ROWS*C_];
__device__ __nv_bfloat16 g_xh[M_ROWS*KDIM], g_xl[M_ROWS*KDIM];
__device__ __nv_bfloat16 g_wah[3*C_*KDIM], g_wal[3*C_*KDIM];
__device__ __nv_bfloat16 g_wph[C_*KDIM], g_wpl[C_*KDIM];
__device__ float g_AK[H_*AL_*HS_];
__device__ float g_AV[H_*AL_*HS_];

// ======================= helpers =======================
__device__ __forceinline__ uint32_t smem_u32(const void* p) {
    uint32_t a;
    asm("{ .reg .u64 t; cvta.to.shared.u64 t, %1; cvt.u32.u64 %0, t; }" : "=r"(a) : "l"(p));
    return a;
}

#define LDSM_X4(r, addr) \
    asm volatile("ldmatrix.sync.aligned.m8n8.x4.shared.b16 {%0,%1,%2,%3}, [%4];" \
        : "=r"((r)[0]), "=r"((r)[1]), "=r"((r)[2]), "=r"((r)[3]) : "r"(addr))

#define LDSM_X4_T(r, addr) \
    asm volatile("ldmatrix.sync.aligned.m8n8.x4.trans.shared.b16 {%0,%1,%2,%3}, [%4];" \
        : "=r"((r)[0]), "=r"((r)[1]), "=r"((r)[2]), "=r"((r)[3]) : "r"(addr))

#define MMA_BF16(d, a, b0, b1) \
    asm volatile("mma.sync.aligned.m16n8k16.row.col.f32.bf16.bf16.f32 " \
        "{%0,%1,%2,%3}, {%4,%5,%6,%7}, {%8,%9}, {%0,%1,%2,%3};" \
        : "+f"((d)[0]), "+f"((d)[1]), "+f"((d)[2]), "+f"((d)[3]) \
        : "r"((a)[0]), "r"((a)[1]), "r"((a)[2]), "r"((a)[3]), "r"(b0), "r"(b1))

#define CP_A16(dst, src) \
    asm volatile("cp.async.cg.shared.global [%0], [%1], 16;" :: "r"(dst), "l"(src))
#define CP_COMMIT() asm volatile("cp.async.commit_group;")
#define CP_WAIT(n)  asm volatile("cp.async.wait_group %0;" :: "n"(n))

// swizzled byte offset inside a [rows][64B] bf16 tile (4x 16B chunks/row)
__device__ __forceinline__ uint32_t tswz(int row, int chunk) {
    return (uint32_t)(row * 64 + ((chunk ^ ((row >> 1) & 3)) << 4));
}

__device__ __forceinline__ void pack2(float a, float b, uint32_t& hi, uint32_t& lo) {
    __nv_bfloat162 th = __floats2bfloat162_rn(a, b);
    __nv_bfloat162 tl = __floats2bfloat162_rn(a - __low2float(th), b - __high2float(th));
    hi = *reinterpret_cast<uint32_t*>(&th);
    lo = *reinterpret_cast<uint32_t*>(&tl);
}

// ======================================================================
// prep: fp32 -> bf16 hi/lo split (elementwise)
// ======================================================================
__global__ __launch_bounds__(256) void conv_split(
    const float4* __restrict__ src, uint2* __restrict__ hi,
    uint2* __restrict__ lo, int n4)
{
    const int i = blockIdx.x * blockDim.x + threadIdx.x;
    if (i >= n4) return;
    const float4 v = src[i];
    uint32_t h0, l0, h1, l1;
    pack2(v.x, v.y, h0, l0);
    pack2(v.z, v.w, h1, l1);
    hi[i] = make_uint2(h0, h1);
    lo[i] = make_uint2(l0, l1);
}

// ======================================================================
// split-bf16 x3 GEMM (NT) with cp.async 3-stage pipeline.
// C[m][n] = sum_k A[m][k]*Bw[n][k], operands pre-split into hi/lo bf16.
// CTA 128x128, KC=32, 256 thr (8 warps 2x4).
// MODE 0: rope + pack -> g_{Q,K,V}{h,l}.   MODE 1: fp32 write to Cout.
// ======================================================================
#define KC 32
#define TILE_B 8192                 // 128 rows x 64B
#define STAGE_B (4*TILE_B)          // Ahi, Alo, Bhi, Blo = 32 KB
#define NSTAGE 3
#define GEMM_SMEM (NSTAGE*STAGE_B)  // 96 KB

template<int MODE>
__global__ __launch_bounds__(256, 1) void tgemm(
    const __nv_bfloat16* __restrict__ Ah, const __nv_bfloat16* __restrict__ Al,
    const __nv_bfloat16* __restrict__ Bh, const __nv_bfloat16* __restrict__ Bl,
    const float* __restrict__ rope, float* __restrict__ Cout)
{
    extern __shared__ __align__(1024) char smx[];
    const uint32_t sb = smem_u32(smx);

    const int tid  = threadIdx.x;
    const int wid  = tid >> 5;
    const int lane = tid & 31;
    const int wm   = wid & 1;
    const int wn   = wid >> 1;
    const int bm   = blockIdx.y << 7;
    const int bn   = blockIdx.x << 7;

    int lrow[2], lchk[2]; uint32_t lsw[2];
    #pragma unroll
    for (int f = 0; f < 2; f++) {
        int idx = tid + (f << 8);
        lrow[f] = idx >> 2; lchk[f] = idx & 3;
        lsw[f] = tswz(lrow[f], lchk[f]);
    }

    const int grp = lane >> 3, lr = lane & 7;
    uint32_t offA[4][2], offB[2][2];
    #pragma unroll
    for (int i = 0; i < 4; i++)
        #pragma unroll
        for (int ks = 0; ks < 2; ks++) {
            int row = wm*64 + i*16 + (grp & 1)*8 + lr;
            offA[i][ks] = tswz(row, (grp >> 1) + 2*ks);
        }
    #pragma unroll
    for (int jj = 0; jj < 2; jj++)
        #pragma unroll
        for (int ks = 0; ks < 2; ks++) {
            int row = wn*32 + jj*16 + (grp >> 1)*8 + lr;
            offB[jj][ks] = tswz(row, (grp & 1) + 2*ks);
        }

    float acc[4][4][4];
    #pragma unroll
    for (int i = 0; i < 4; i++)
        #pragma unroll
        for (int j = 0; j < 4; j++)
            #pragma unroll
            for (int c = 0; c < 4; c++) acc[i][j][c] = 0.f;

    const __nv_bfloat16* Abh = Ah + (long)bm * KDIM;
    const __nv_bfloat16* Abl = Al + (long)bm * KDIM;
    const __nv_bfloat16* Bbh = Bh + (long)bn * KDIM;
    const __nv_bfloat16* Bbl = Bl + (long)bn * KDIM;

    auto load_stage = [&](int c, int s) {
        const uint32_t st = sb + (uint32_t)s * STAGE_B;
        const long kb = (long)c * KC;
        #pragma unroll
        for (int f = 0; f < 2; f++) {
            const long ga = (long)lrow[f]*KDIM + kb + lchk[f]*8;
            CP_A16(st + 0*TILE_B + lsw[f], Abh + ga);
            CP_A16(st + 1*TILE_B + lsw[f], Abl + ga);
            CP_A16(st + 2*TILE_B + lsw[f], Bbh + ga);
            CP_A16(st + 3*TILE_B + lsw[f], Bbl + ga);
        }
        CP_COMMIT();
    };

    const int NCH = KDIM / KC;     // 64
    load_stage(0, 0);
    load_stage(1, 1);

    for (int c = 0; c < NCH; c++) {
        CP_WAIT(1);
        __syncthreads();

        const uint32_t stg = sb + (uint32_t)(c % NSTAGE) * STAGE_B;
        #pragma unroll
        for (int ks = 0; ks < 2; ks++) {
            uint32_t ah[4][4], al[4][4], bh[2][4], bl[2][4];
            #pragma unroll
            for (int i = 0; i < 4; i++) {
                LDSM_X4(ah[i], stg + 0*TILE_B + offA[i][ks]);
                LDSM_X4(al[i], stg + 1*TILE_B + offA[i][ks]);
            }
            #pragma unroll
            for (int jj = 0; jj < 2; jj++) {
                LDSM_X4(bh[jj], stg + 2*TILE_B + offB[jj][ks]);
                LDSM_X4(bl[jj], stg + 3*TILE_B + offB[jj][ks]);
            }
            #pragma unroll
            for (int i = 0; i < 4; i++)
                #pragma unroll
                for (int j = 0; j < 4; j++) {
                    const int jj = j >> 1, jo = (j & 1) << 1;
                    MMA_BF16(acc[i][j], ah[i], bh[jj][jo], bh[jj][jo+1]);
                    MMA_BF16(acc[i][j], ah[i], bl[jj][jo], bl[jj][jo+1]);
                    MMA_BF16(acc[i][j], al[i], bh[jj][jo], bh[jj][jo+1]);
                }
        }

        if (c + 2 < NCH) load_stage(c + 2, (c + 2) % NSTAGE);
        else CP_COMMIT();
    }

    // ---------------- epilogue ----------------
    const int lr4 = lane >> 2;
    const int lc2 = (lane & 3) << 1;

    if (MODE == 0) {
        const int sel = bn >> 11;
        const int hh  = (bn & 2047) >> 7;
        __nv_bfloat16* baseH = (sel == 0 ? g_Qh : (sel == 1 ? g_Kh : g_Vh));
        __nv_bfloat16* baseL = (sel == 0 ? g_Ql : (sel == 1 ? g_Kl : g_Vl));
        #pragma unroll
        for (int i = 0; i < 4; i++) {
            #pragma unroll
            for (int j = 0; j < 4; j++) {
                const int d = wn*32 + j*8 + lc2;
                #pragma unroll
                for (int rh = 0; rh < 2; rh++) {
                    const int m = bm + wm*64 + i*16 + lr4 + rh*8;
                    const int b = m >> 11, t = m & 2047;
                    float v0 = acc[i][j][rh*2], v1 = acc[i][j][rh*2+1];
                    if (sel < 2) {
                        const float2 rr = *(const float2*)(rope + (long)t*128 + d);
                        const float o0 = v0*rr.x - v1*rr.y;
                        const float o1 = v1*rr.x + v0*rr.y;
                        v0 = o0; v1 = o1;
                    }
                    uint32_t hi, lo; pack2(v0, v1, hi, lo);
                    const long idx = ((long)(b*H_ + hh)*T_ + t)*HS_ + d;
                    *(uint32_t*)((uint16_t*)baseH + idx) = hi;
                    *(uint32_t*)((uint16_t*)baseL + idx) = lo;
                }
            }
        }
    } else {
        #pragma unroll
        for (int i = 0; i < 4; i++)
            #pragma unroll
            for (int j = 0; j < 4; j++) {
                const int ncol = bn + wn*32 + j*8 + lc2;
                #pragma unroll
                for (int rh = 0; rh < 2; rh++) {
                    const int m = bm + wm*64 + i*16 + lr4 + rh*8;
                    *(float2*)(Cout + (long)m*C_ + ncol) =
                        make_float2(acc[i][j][rh*2], acc[i][j][rh*2+1]);
                }
            }
    }
}

// ======================================================================
// Adapter K/V (unchanged; fp32)
// ======================================================================
__global__ __launch_bounds__(128) void adapter_kv(
    const float* __restrict__ W, const float* __restrict__ emb)
{
    const int bx = blockIdx.x;
    const int np = 2048 + bx;
    const float* wrow = W + (long)np * KDIM;

    float part[AL_] = {};
    for (int k = threadIdx.x; k < KDIM; k += 128) {
        float w = wrow[k];
        #pragma unroll
        for (int j = 0; j < AL_; j++) part[j] += w * emb[j*KDIM + k];
    }
    #pragma unroll
    for (int j = 0; j < AL_; j++)
        #pragma unroll
        for (int off = 16; off; off >>= 1)
            part[j] += __shfl_xor_sync(0xffffffffu, part[j], off);

    __shared__ float red[AL_][4];
    const int w = threadIdx.x >> 5, lane = threadIdx.x & 31;
    if (lane == 0)
        #pragma unroll
        for (int j = 0; j < AL_; j++) red[j][w] = part[j];
    __syncthreads();
    if (threadIdx.x < AL_) {
        const int j = threadIdx.x;
        float s = red[j][0] + red[j][1] + red[j][2] + red[j][3];
        const int isv = bx >> 11;
        const int nn  = bx & 2047;
        const int h   = nn >> 7, d = nn & 127;
        float* dst = isv ? g_AV : g_AK;
        dst[(h*AL_ + j)*HS_ + d] = s;
    }
}

// ======================================================================
// Flash attention (split-bf16 x3 tensor cores), cp.async loads of
// pre-split Q/K/V, 2-stage KV pipeline, fused adapter + gating.
// BM=128, BN=64, 8 warps.
// ======================================================================
#define FQHI 0
#define FQLO 32768
#define FKV  65536
#define KVSTAGE_B 65536          // Kh,Kl,Vh,Vl x 16KB
#define FAK  (FKV + 2*KVSTAGE_B)             // 196608
#define FAV  (FAK + AL_*HS_*4)               // 201728
#define FLASH_SMEM (FAV + AL_*HS_*4)         // 206848

__global__ __launch_bounds__(256, 1) void flash_mma(const float* __restrict__ gating)
{
    extern __shared__ __align__(1024) char fsm[];
    const uint32_t sb = smem_u32(fsm);

    const int tid  = threadIdx.x;
    const int w    = tid >> 5;
    const int lane = tid & 31;
    const int grp  = lane >> 3, lr = lane & 7;
    const int lam  = lane & 3;
    const int rsub = lane >> 2;

    const int qb = (gridDim.x - 1) - blockIdx.x;
    const int bhI = blockIdx.y;
    const int h  = bhI & 15;
    const int b  = bhI >> 4;

    const __nv_bfloat16* Qhg = g_Qh + (long)bhI*T_*HS_ + (long)qb*128*HS_;
    const __nv_bfloat16* Qlg = g_Ql + (long)bhI*T_*HS_ + (long)qb*128*HS_;
    const __nv_bfloat16* Khg = g_Kh + (long)bhI*T_*HS_;
    const __nv_bfloat16* Klg = g_Kl + (long)bhI*T_*HS_;
    const __nv_bfloat16* Vhg = g_Vh + (long)bhI*T_*HS_;
    const __nv_bfloat16* Vlg = g_Vl + (long)bhI*T_*HS_;

    // ---- group 0: Q tiles (hi+lo) ----
    #pragma unroll
    for (int f = 0; f < 8; f++) {
        const int slot = tid + (f << 8);           // 0..2047
        const int row = slot >> 4, c8 = slot & 15;
        const uint32_t off = (uint32_t)((c8 >> 2) * 8192) + tswz(row, c8 & 3);
        const long g = (long)row*HS_ + c8*8;
        CP_A16(sb + FQHI + off, Qhg + g);
        CP_A16(sb + FQLO + off, Qlg + g);
    }
    CP_COMMIT();

    auto load_kv = [&](int kb) {
        const uint32_t st = sb + FKV + (uint32_t)(kb & 1) * KVSTAGE_B;
        const long gb = (long)kb*64*HS_;
        #pragma unroll
        for (int f = 0; f < 4; f++) {
            const int slot = tid + (f << 8);       // 0..1023
            const int row = slot >> 4, c8 = slot & 15;
            const uint32_t off = (uint32_t)((c8 >> 2) * 4096) + tswz(row, c8 & 3);
            const long g = gb + (long)row*HS_ + c8*8;
            CP_A16(st + 0     + off, Khg + g);
            CP_A16(st + 16384 + off, Klg + g);
            CP_A16(st + 32768 + off, Vhg + g);
            CP_A16(st + 49152 + off, Vlg + g);
        }
        CP_COMMIT();
    };

    // ---- adapter tiles (fp32, plain stores) ----
    {
        const float4* AKg = (const float4*)(g_AK + h*AL_*HS_);
        const float4* AVg = (const float4*)(g_AV + h*AL_*HS_);
        for (int i = tid; i < AL_*HS_/4; i += 256) {
            ((float4*)(fsm + FAK))[i] = AKg[i];
            ((float4*)(fsm + FAV))[i] = AVg[i];
        }
    }

    float O[16][4];
    #pragma unroll
    for (int nf = 0; nf < 16; nf++)
        #pragma unroll
        for (int c = 0; c < 4; c++) O[nf][c] = 0.f;
    float m0 = NEG_BIG, m1 = NEG_BIG, l0 = 0.f, l1 = 0.f;
    const float scale = 0.08838834764831843f;

    const int rowg0 = qb*128 + 16*w + rsub;
    const int warp_rmax = qb*128 + 16*w + 15;

    const int kmax = 2*qb + 2;
    load_kv(0);                                   // group 1

    for (int kb = 0; kb < kmax; kb++) {
        if (kb + 1 < kmax) load_kv(kb + 1);
        else CP_COMMIT();
        CP_WAIT(1);
        __syncthreads();

        if (kb*64 <= warp_rmax) {
            const uint32_t kvst = sb + FKV + (uint32_t)(kb & 1) * KVSTAGE_B;

            // ---- S = Q K^T ----
            float S[8][4];
            #pragma unroll
            for (int j = 0; j < 8; j++)
                #pragma unroll
                for (int c = 0; c < 4; c++) S[j][c] = 0.f;

            #pragma unroll
            for (int ks = 0; ks < 8; ks++) {
                const int tQ = ks >> 1, chb = (ks & 1) << 1;
                const int arow = 16*w + (grp & 1)*8 + lr;
                const uint32_t aoff = (uint32_t)(tQ*8192) + tswz(arow, chb + (grp >> 1));
                uint32_t ah[4], al[4];
                LDSM_X4(ah, sb + FQHI + aoff);
                LDSM_X4(al, sb + FQLO + aoff);
                #pragma unroll
                for (int jj = 0; jj < 4; jj++) {
                    const int brow = jj*16 + (grp >> 1)*8 + lr;
                    const uint32_t boff = (uint32_t)(tQ*4096) + tswz(brow, (grp & 1) + chb);
                    uint32_t kh[4], kl[4];
                    LDSM_X4(kh, kvst + 0     + boff);
                    LDSM_X4(kl, kvst + 16384 + boff);
                    #pragma unroll
                    for (int j2 = 0; j2 < 2; j2++) {
                        const int j = jj*2 + j2, jo = j2 << 1;
                        MMA_BF16(S[j], ah, kh[jo], kh[jo+1]);
                        MMA_BF16(S[j], ah, kl[jo], kl[jo+1]);
                        MMA_BF16(S[j], al, kh[jo], kh[jo+1]);
                    }
                }
            }

            // ---- scale + mask ----
            const bool needMask = (kb*64 + 63) > (qb*128 + 16*w);
            #pragma unroll
            for (int j = 0; j < 8; j++)
                #pragma unroll
                for (int c = 0; c < 4; c++) {
                    float sv = S[j][c] * scale;
                    if (needMask) {
                        const int colg = kb*64 + j*8 + 2*lam + (c & 1);
                        const int rowg = rowg0 + ((c >> 1) << 3);
                        if (colg > rowg) sv = NEG_BIG;
                    }
                    S[j][c] = sv;
                }

            // ---- online softmax ----
            float mx0 = S[0][0], mx1 = S[0][2];
            #pragma unroll
            for (int j = 0; j < 8; j++) {
                mx0 = fmaxf(mx0, fmaxf(S[j][0], S[j][1]));
                mx1 = fmaxf(mx1, fmaxf(S[j][2], S[j][3]));
            }
            mx0 = fmaxf(mx0, __shfl_xor_sync(0xffffffffu, mx0, 1));
            mx0 = fmaxf(mx0, __shfl_xor_sync(0xffffffffu, mx0, 2));
            mx1 = fmaxf(mx1, __shfl_xor_sync(0xffffffffu, mx1, 1));
            mx1 = fmaxf(mx1, __shfl_xor_sync(0xffffffffu, mx1, 2));
            const float mn0 = fmaxf(m0, mx0);
            const float mn1 = fmaxf(m1, mx1);
            const float corr0 = __expf(m0 - mn0);
            const float corr1 = __expf(m1 - mn1);
            float rs0 = 0.f, rs1 = 0.f;
            #pragma unroll
            for (int j = 0; j < 8; j++) {
                S[j][0] = __expf(S[j][0] - mn0);
                S[j][1] = __expf(S[j][1] - mn0);
                S[j][2] = __expf(S[j][2] - mn1);
                S[j][3] = __expf(S[j][3] - mn1);
                rs0 += S[j][0] + S[j][1];
                rs1 += S[j][2] + S[j][3];
            }
            l0 = l0*corr0 + rs0;
            l1 = l1*corr1 + rs1;
            m0 = mn0; m1 = mn1;
            #pragma unroll
            for (int nf = 0; nf < 16; nf++) {
                O[nf][0] *= corr0; O[nf][1] *= corr0;
                O[nf][2] *= corr1; O[nf][3] *= corr1;
            }

            // ---- O += P V ----
            #pragma unroll
            for (int ks2 = 0; ks2 < 4; ks2++) {
                const int j0 = 2*ks2, j1 = j0 + 1;
                uint32_t phi[4], plo[4];
                pack2(S[j0][0], S[j0][1], phi[0], plo[0]);
                pack2(S[j0][2], S[j0][3], phi[1], plo[1]);
                pack2(S[j1][0], S[j1][1], phi[2], plo[2]);
                pack2(S[j1][2], S[j1][3], phi[3], plo[3]);
                #pragma unroll
                for (int nc = 0; nc < 8; nc++) {
                    const int vrow = ks2*16 + (grp & 1)*8 + lr;
                    const uint32_t voff = (uint32_t)((nc >> 1) * 4096)
                                        + tswz(vrow, ((nc & 1) << 1) + (grp >> 1));
                    uint32_t vh[4], vl[4];
                    LDSM_X4_T(vh, kvst + 32768 + voff);
                    LDSM_X4_T(vl, kvst + 49152 + voff);
                    MMA_BF16(O[2*nc],   phi, vh[0], vh[1]);
                    MMA_BF16(O[2*nc+1], phi, vh[2], vh[3]);
                    MMA_BF16(O[2*nc],   phi, vl[0], vl[1]);
                    MMA_BF16(O[2*nc+1], phi, vl[2], vl[3]);
                    MMA_BF16(O[2*nc],   plo, vh[0], vh[1]);
                    MMA_BF16(O[2*nc+1], plo, vh[2], vh[3]);
                }
            }
        }
        __syncthreads();
    }

    // ---- finalize l ----
    l0 += __shfl_xor_sync(0xffffffffu, l0, 1);
    l0 += __shfl_xor_sync(0xffffffffu, l0, 2);
    l1 += __shfl_xor_sync(0xffffffffu, l1, 1);
    l1 += __shfl_xor_sync(0xffffffffu, l1, 2);

    // ---- adapter attention (q = hi+lo from smem) ----
    float sa0[AL_], sa1[AL_];
    #pragma unroll
    for (int j = 0; j < AL_; j++) { sa0[j] = 0.f; sa1[j] = 0.f; }
    const float* AKs = (const float*)(fsm + FAK);
    const float* AVs = (const float*)(fsm + FAV);
    #pragma unroll
    for (int rr = 0; rr < 2; rr++) {
        const int rowL = 16*w + rsub + rr*8;
        float* sa = rr ? sa1 : sa0;
        #pragma unroll
        for (int ch = 0; ch < 4; ch++) {
            const uint32_t off = (uint32_t)(lam * 8192) + tswz(rowL, ch);
            uint4 qh = *(const uint4*)(fsm + FQHI + off);
            uint4 ql = *(const uint4*)(fsm + FQLO + off);
            const uint32_t* qhp = (const uint32_t*)&qh;
            const uint32_t* qlp = (const uint32_t*)&ql;
            float q[8];
            #pragma unroll
            for (int e = 0; e < 4; e++) {
                __nv_bfloat162 bh2 = *reinterpret_cast<const __nv_bfloat162*>(&qhp[e]);
                __nv_bfloat162 bl2 = *reinterpret_cast<const __nv_bfloat162*>(&qlp[e]);
                q[2*e]   = __low2float(bh2)  + __low2float(bl2);
                q[2*e+1] = __high2float(bh2) + __high2float(bl2);
            }
            const int d0 = lam*32 + ch*8;
            #pragma unroll
            for (int j = 0; j < AL_; j++) {
                const float* ak = AKs + j*HS_ + d0;
                #pragma unroll
                for (int e = 0; e < 8; e++) sa[j] += q[e] * ak[e];
            }
        }
    }
    #pragma unroll
    for (int j = 0; j < AL_; j++) {
        sa0[j] += __shfl_xor_sync(0xffffffffu, sa0[j], 1);
        sa0[j] += __shfl_xor_sync(0xffffffffu, sa0[j], 2);
        sa1[j] += __shfl_xor_sync(0xffffffffu, sa1[j], 1);
        sa1[j] += __shfl_xor_sync(0xffffffffu, sa1[j], 2);
    }

    const float g = gating[h];
    #pragma unroll
    for (int rr = 0; rr < 2; rr++) {
        float* sa = rr ? sa1 : sa0;
        const float li = rr ? l1 : l0;
        const int rowg = rowg0 + rr*8;
        float mx = sa[0]*scale;
        #pragma unroll
        for (int j = 1; j < AL_; j++) mx = fmaxf(mx, sa[j]*scale);
        float pa[AL_], ssum = 0.f;
        #pragma unroll
        for (int j = 0; j < AL_; j++) { pa[j] = __expf(sa[j]*scale - mx); ssum += pa[j]; }
        const float pg = g / ssum;
        const float inv_l = 1.f / li;
        const long yidx0 = ((long)b*T_ + rowg)*C_ + h*HS_;
        #pragma unroll
        for (int nf = 0; nf < 16; nf++) {
            const int d = nf*8 + 2*lam;
            float o0 = O[nf][rr*2]   * inv_l;
            float o1 = O[nf][rr*2+1] * inv_l;
            #pragma unroll
            for (int j = 0; j < AL_; j++) {
                const float p = pa[j] * pg;
                o0 += p * AVs[j*HS_ + d];
                o1 += p * AVs[j*HS_ + d + 1];
            }
            uint32_t hi, lo; pack2(o0, o1, hi, lo);
            *(uint32_t*)((uint16_t*)g_Yh + yidx0 + d) = hi;
            *(uint32_t*)((uint16_t*)g_Yl + yidx0 + d) = lo;
        }
    }
}

// ======================================================================
extern "C" void kernel_launch(void* const* d_in, const int* in_sizes, int n_in,
                              void* d_out, int out_size)
{
    const float* x      = (const float*)d_in[0];
    const float* rope   = (const float*)d_in[1];
    const float* W_attn = (const float*)d_in[3];
    const float* W_proj = (const float*)d_in[4];
    const float* emb    = (const float*)d_in[5];
    const float* gating = (const float*)d_in[6];
    float* out = (float*)d_out;

    void *xh, *xl, *wah, *wal, *wph, *wpl, *yh, *yl;
    cudaGetSymbolAddress(&xh,  g_xh);  cudaGetSymbolAddress(&xl,  g_xl);
    cudaGetSymbolAddress(&wah, g_wah); cudaGetSymbolAddress(&wal, g_wal);
    cudaGetSymbolAddress(&wph, g_wph); cudaGetSymbolAddress(&wpl, g_wpl);
    cudaGetSymbolAddress(&yh,  g_Yh);  cudaGetSymbolAddress(&yl,  g_Yl);

    cudaFuncSetAttribute(tgemm<0>, cudaFuncAttributeMaxDynamicSharedMemorySize, GEMM_SMEM);
    cudaFuncSetAttribute(tgemm<1>, cudaFuncAttributeMaxDynamicSharedMemorySize, GEMM_SMEM);
    cudaFuncSetAttribute(flash_mma, cudaFuncAttributeMaxDynamicSharedMemorySize, FLASH_SMEM);

    // 0) split inputs into bf16 hi/lo
    {
        int n4;
        n4 = M_ROWS*KDIM/4;
        conv_split<<<(n4+255)/256, 256>>>((const float4*)x, (uint2*)xh, (uint2*)xl, n4);
        n4 = 3*C_*KDIM/4;
        conv_split<<<(n4+255)/256, 256>>>((const float4*)W_attn, (uint2*)wah, (uint2*)wal, n4);
        n4 = C_*KDIM/4;
        conv_split<<<(n4+255)/256, 256>>>((const float4*)W_proj, (uint2*)wph, (uint2*)wpl, n4);
    }
    // 1) QKV GEMM + rope -> split Q/K/V
    tgemm<0><<<dim3(48, 32), 256, GEMM_SMEM>>>(
        (const __nv_bfloat16*)xh, (const __nv_bfloat16*)xl,
        (const __nv_bfloat16*)wah, (const __nv_bfloat16*)wal, rope, nullptr);
    // 2) adapter k/v
    adapter_kv<<<4096, 128>>>(W_attn, emb);
    // 3) flash attention + fused adapter/gating -> split Y
    flash_mma<<<dim3(T_/128, B_*H_), 256, FLASH_SMEM>>>(gating);
    // 4) output projection -> fp32 out
    tgemm<1><<<dim3(16, 32), 256, GEMM_SMEM>>>(
        (const __nv_bfloat16*)yh, (const __nv_bfloat16*)yl,
        (const __nv_bfloat16*)wph, (const __nv_bfloat16*)wpl, nullptr, out);
}

// round 6
// speedup vs baseline: 2.9848x; 1.0224x over previous
#include <cuda_runtime.h>
#include <cuda_bf16.h>
#include <math.h>
#include <stdint.h>

// Problem constants
#define B_ 2
#define T_ 2048
#define C_ 2048
#define H_ 16
#define HS_ 128
#define AL_ 10
#define KDIM 2048
#define M_ROWS 4096

#define NEG_BIG (-1e30f)

// ---------------- scratch: split-bf16 tensors ----------------
#define QKV_ELEMS (B_*H_*T_*HS_)
__device__ __nv_bfloat16 g_Qh[QKV_ELEMS], g_Ql[QKV_ELEMS];
__device__ __nv_bfloat16 g_Kh[QKV_ELEMS], g_Kl[QKV_ELEMS];
__device__ __nv_bfloat16 g_Vh[QKV_ELEMS], g_Vl[QKV_ELEMS];
__device__ __nv_bfloat16 g_Yh[M_ROWS*C_], g_Yl[M_ROWS*C_];
__device__ __nv_bfloat16 g_xh[M_ROWS*KDIM], g_xl[M_ROWS*KDIM];
__device__ __nv_bfloat16 g_wah[3*C_*KDIM], g_wal[3*C_*KDIM];
__device__ __nv_bfloat16 g_wph[C_*KDIM], g_wpl[C_*KDIM];
__device__ float g_AK[H_*AL_*HS_];
__device__ float g_AV[H_*AL_*HS_];

// ======================= helpers =======================
__device__ __forceinline__ uint32_t smem_u32(const void* p) {
    uint32_t a;
    asm("{ .reg .u64 t; cvta.to.shared.u64 t, %1; cvt.u32.u64 %0, t; }" : "=r"(a) : "l"(p));
    return a;
}

#define LDSM_X4(r, addr) \
    asm volatile("ldmatrix.sync.aligned.m8n8.x4.shared.b16 {%0,%1,%2,%3}, [%4];" \
        : "=r"((r)[0]), "=r"((r)[1]), "=r"((r)[2]), "=r"((r)[3]) : "r"(addr))

#define LDSM_X4_T(r, addr) \
    asm volatile("ldmatrix.sync.aligned.m8n8.x4.trans.shared.b16 {%0,%1,%2,%3}, [%4];" \
        : "=r"((r)[0]), "=r"((r)[1]), "=r"((r)[2]), "=r"((r)[3]) : "r"(addr))

#define MMA_BF16(d, a, b0, b1) \
    asm volatile("mma.sync.aligned.m16n8k16.row.col.f32.bf16.bf16.f32 " \
        "{%0,%1,%2,%3}, {%4,%5,%6,%7}, {%8,%9}, {%0,%1,%2,%3};" \
        : "+f"((d)[0]), "+f"((d)[1]), "+f"((d)[2]), "+f"((d)[3]) \
        : "r"((a)[0]), "r"((a)[1]), "r"((a)[2]), "r"((a)[3]), "r"(b0), "r"(b1))

#define CP_A16(dst, src) \
    asm volatile("cp.async.cg.shared.global [%0], [%1], 16;" :: "r"(dst), "l"(src))
#define CP_COMMIT() asm volatile("cp.async.commit_group;")
#define CP_WAIT(n)  asm volatile("cp.async.wait_group %0;" :: "n"(n))

// swizzled byte offset inside a [rows][64B] bf16 tile (4x 16B chunks/row)
__device__ __forceinline__ uint32_t tswz(int row, int chunk) {
    return (uint32_t)(row * 64 + ((chunk ^ ((row >> 1) & 3)) << 4));
}

__device__ __forceinline__ void pack2(float a, float b, uint32_t& hi, uint32_t& lo) {
    __nv_bfloat162 th = __floats2bfloat162_rn(a, b);
    __nv_bfloat162 tl = __floats2bfloat162_rn(a - __low2float(th), b - __high2float(th));
    hi = *reinterpret_cast<uint32_t*>(&th);
    lo = *reinterpret_cast<uint32_t*>(&tl);
}

// ======================================================================
// prep: fp32 -> bf16 hi/lo split (elementwise)
// ======================================================================
__global__ __launch_bounds__(256) void conv_split(
    const float4* __restrict__ src, uint2* __restrict__ hi,
    uint2* __restrict__ lo, int n4)
{
    const int i = blockIdx.x * blockDim.x + threadIdx.x;
    if (i >= n4) return;
    const float4 v = src[i];
    uint32_t h0, l0, h1, l1;
    pack2(v.x, v.y, h0, l0);
    pack2(v.z, v.w, h1, l1);
    hi[i] = make_uint2(h0, h1);
    lo[i] = make_uint2(l0, l1);
}

// ======================================================================
// split-bf16 x3 GEMM (NT), cp.async 3-stage pipeline, KC=64.
// Stage layout (64KB): Ahi[2x8K] Alo[2x8K] Bhi[2x8K] Blo[2x8K]
// (two 8KB sub-tiles = k 0..31 / 32..63, each with the 64B-row swizzle).
// MODE 0: rope + pack -> g_{Q,K,V}{h,l}.   MODE 1: fp32 write to Cout.
// ======================================================================
#define KC 64
#define SUB_B 8192
#define STAGE_B 65536
#define NSTAGE 3
#define GEMM_SMEM (NSTAGE*STAGE_B)   // 192 KB

template<int MODE>
__global__ __launch_bounds__(256, 1) void tgemm(
    const __nv_bfloat16* __restrict__ Ah, const __nv_bfloat16* __restrict__ Al,
    const __nv_bfloat16* __restrict__ Bh, const __nv_bfloat16* __restrict__ Bl,
    const float* __restrict__ rope, float* __restrict__ Cout)
{
    extern __shared__ __align__(1024) char smx[];
    const uint32_t sb = smem_u32(smx);

    const int tid  = threadIdx.x;
    const int wid  = tid >> 5;
    const int lane = tid & 31;
    const int wm   = wid & 1;
    const int wn   = wid >> 1;
    const int bm   = blockIdx.y << 7;
    const int bn   = blockIdx.x << 7;

    // load slots: f in 0..3, idx = tid + 256f in [0,1024): row = idx>>3, cq = idx&7
    int lrow[4], lchk[4]; uint32_t lsw[4];
    #pragma unroll
    for (int f = 0; f < 4; f++) {
        int idx = tid + (f << 8);
        lrow[f] = idx >> 3; lchk[f] = idx & 7;
        lsw[f] = (uint32_t)((lchk[f] >> 2) * SUB_B) + tswz(lrow[f], lchk[f] & 3);
    }

    const int grp = lane >> 3, lr = lane & 7;
    uint32_t offA[4][2], offB[2][2];
    #pragma unroll
    for (int i = 0; i < 4; i++)
        #pragma unroll
        for (int ks = 0; ks < 2; ks++) {
            int row = wm*64 + i*16 + (grp & 1)*8 + lr;
            offA[i][ks] = tswz(row, (grp >> 1) + 2*ks);
        }
    #pragma unroll
    for (int jj = 0; jj < 2; jj++)
        #pragma unroll
        for (int ks = 0; ks < 2; ks++) {
            int row = wn*32 + jj*16 + (grp >> 1)*8 + lr;
            offB[jj][ks] = tswz(row, (grp & 1) + 2*ks);
        }

    float acc[4][4][4];
    #pragma unroll
    for (int i = 0; i < 4; i++)
        #pragma unroll
        for (int j = 0; j < 4; j++)
            #pragma unroll
            for (int c = 0; c < 4; c++) acc[i][j][c] = 0.f;

    const __nv_bfloat16* Abh = Ah + (long)bm * KDIM;
    const __nv_bfloat16* Abl = Al + (long)bm * KDIM;
    const __nv_bfloat16* Bbh = Bh + (long)bn * KDIM;
    const __nv_bfloat16* Bbl = Bl + (long)bn * KDIM;

    auto load_stage = [&](int c, int s) {
        const uint32_t st = sb + (uint32_t)s * STAGE_B;
        const long kb = (long)c * KC;
        #pragma unroll
        for (int f = 0; f < 4; f++) {
            const long ga = (long)lrow[f]*KDIM + kb + lchk[f]*8;
            CP_A16(st + 0*16384 + lsw[f], Abh + ga);
            CP_A16(st + 1*16384 + lsw[f], Abl + ga);
            CP_A16(st + 2*16384 + lsw[f], Bbh + ga);
            CP_A16(st + 3*16384 + lsw[f], Bbl + ga);
        }
        CP_COMMIT();
    };

    const int NCH = KDIM / KC;     // 32
    load_stage(0, 0);
    load_stage(1, 1);

    for (int c = 0; c < NCH; c++) {
        CP_WAIT(1);
        __syncthreads();

        const uint32_t stg = sb + (uint32_t)(c % NSTAGE) * STAGE_B;
        #pragma unroll
        for (int ks = 0; ks < 4; ks++) {
            const int kh2 = ks & 1;
            const uint32_t sub = stg + (uint32_t)((ks >> 1) * SUB_B);
            uint32_t ah[4][4], al[4][4], bh[2][4], bl[2][4];
            #pragma unroll
            for (int i = 0; i < 4; i++) {
                LDSM_X4(ah[i], sub + 0*16384 + offA[i][kh2]);
                LDSM_X4(al[i], sub + 1*16384 + offA[i][kh2]);
            }
            #pragma unroll
            for (int jj = 0; jj < 2; jj++) {
                LDSM_X4(bh[jj], sub + 2*16384 + offB[jj][kh2]);
                LDSM_X4(bl[jj], sub + 3*16384 + offB[jj][kh2]);
            }
            #pragma unroll
            for (int i = 0; i < 4; i++)
                #pragma unroll
                for (int j = 0; j < 4; j++) {
                    const int jj = j >> 1, jo = (j & 1) << 1;
                    MMA_BF16(acc[i][j], ah[i], bh[jj][jo], bh[jj][jo+1]);
                    MMA_BF16(acc[i][j], ah[i], bl[jj][jo], bl[jj][jo+1]);
                    MMA_BF16(acc[i][j], al[i], bh[jj][jo], bh[jj][jo+1]);
                }
        }

        if (c + 2 < NCH) load_stage(c + 2, (c + 2) % NSTAGE);
        else CP_COMMIT();
    }

    // ---------------- epilogue ----------------
    const int lr4 = lane >> 2;
    const int lc2 = (lane & 3) << 1;

    if (MODE == 0) {
        const int sel = bn >> 11;
        const int hh  = (bn & 2047) >> 7;
        __nv_bfloat16* baseH = (sel == 0 ? g_Qh : (sel == 1 ? g_Kh : g_Vh));
        __nv_bfloat16* baseL = (sel == 0 ? g_Ql : (sel == 1 ? g_Kl : g_Vl));
        #pragma unroll
        for (int i = 0; i < 4; i++) {
            #pragma unroll
            for (int j = 0; j < 4; j++) {
                const int d = wn*32 + j*8 + lc2;
                #pragma unroll
                for (int rh = 0; rh < 2; rh++) {
                    const int m = bm + wm*64 + i*16 + lr4 + rh*8;
                    const int b = m >> 11, t = m & 2047;
                    float v0 = acc[i][j][rh*2], v1 = acc[i][j][rh*2+1];
                    if (sel < 2) {
                        const float2 rr = *(const float2*)(rope + (long)t*128 + d);
                        const float o0 = v0*rr.x - v1*rr.y;
                        const float o1 = v1*rr.x + v0*rr.y;
                        v0 = o0; v1 = o1;
                    }
                    uint32_t hi, lo; pack2(v0, v1, hi, lo);
                    const long idx = ((long)(b*H_ + hh)*T_ + t)*HS_ + d;
                    *(uint32_t*)((uint16_t*)baseH + idx) = hi;
                    *(uint32_t*)((uint16_t*)baseL + idx) = lo;
                }
            }
        }
    } else {
        #pragma unroll
        for (int i = 0; i < 4; i++)
            #pragma unroll
            for (int j = 0; j < 4; j++) {
                const int ncol = bn + wn*32 + j*8 + lc2;
                #pragma unroll
                for (int rh = 0; rh < 2; rh++) {
                    const int m = bm + wm*64 + i*16 + lr4 + rh*8;
                    *(float2*)(Cout + (long)m*C_ + ncol) =
                        make_float2(acc[i][j][rh*2], acc[i][j][rh*2+1]);
                }
            }
    }
}

// ======================================================================
// Adapter K/V (unchanged; fp32)
// ======================================================================
__global__ __launch_bounds__(128) void adapter_kv(
    const float* __restrict__ W, const float* __restrict__ emb)
{
    const int bx = blockIdx.x;
    const int np = 2048 + bx;
    const float* wrow = W + (long)np * KDIM;

    float part[AL_] = {};
    for (int k = threadIdx.x; k < KDIM; k += 128) {
        float w = wrow[k];
        #pragma unroll
        for (int j = 0; j < AL_; j++) part[j] += w * emb[j*KDIM + k];
    }
    #pragma unroll
    for (int j = 0; j < AL_; j++)
        #pragma unroll
        for (int off = 16; off; off >>= 1)
            part[j] += __shfl_xor_sync(0xffffffffu, part[j], off);

    __shared__ float red[AL_][4];
    const int w = threadIdx.x >> 5, lane = threadIdx.x & 31;
    if (lane == 0)
        #pragma unroll
        for (int j = 0; j < AL_; j++) red[j][w] = part[j];
    __syncthreads();
    if (threadIdx.x < AL_) {
        const int j = threadIdx.x;
        float s = red[j][0] + red[j][1] + red[j][2] + red[j][3];
        const int isv = bx >> 11;
        const int nn  = bx & 2047;
        const int h   = nn >> 7, d = nn & 127;
        float* dst = isv ? g_AV : g_AK;
        dst[(h*AL_ + j)*HS_ + d] = s;
    }
}

// ======================================================================
// Flash attention (split-bf16 x3 tensor cores), cp.async loads of
// pre-split Q/K/V, 2-stage KV pipeline, fused adapter + gating.
// BM=128, BN=64, 8 warps.
// ======================================================================
#define FQHI 0
#define FQLO 32768
#define FKV  65536
#define KVSTAGE_B 65536          // Kh,Kl,Vh,Vl x 16KB
#define FAK  (FKV + 2*KVSTAGE_B)             // 196608
#define FAV  (FAK + AL_*HS_*4)               // 201728
#define FLASH_SMEM (FAV + AL_*HS_*4)         // 206848

__global__ __launch_bounds__(256, 1) void flash_mma(const float* __restrict__ gating)
{
    extern __shared__ __align__(1024) char fsm[];
    const uint32_t sb = smem_u32(fsm);

    const int tid  = threadIdx.x;
    const int w    = tid >> 5;
    const int lane = tid & 31;
    const int grp  = lane >> 3, lr = lane & 7;
    const int lam  = lane & 3;
    const int rsub = lane >> 2;

    const int qb = (gridDim.x - 1) - blockIdx.x;
    const int bhI = blockIdx.y;
    const int h  = bhI & 15;
    const int b  = bhI >> 4;

    const __nv_bfloat16* Qhg = g_Qh + (long)bhI*T_*HS_ + (long)qb*128*HS_;
    const __nv_bfloat16* Qlg = g_Ql + (long)bhI*T_*HS_ + (long)qb*128*HS_;
    const __nv_bfloat16* Khg = g_Kh + (long)bhI*T_*HS_;
    const __nv_bfloat16* Klg = g_Kl + (long)bhI*T_*HS_;
    const __nv_bfloat16* Vhg = g_Vh + (long)bhI*T_*HS_;
    const __nv_bfloat16* Vlg = g_Vl + (long)bhI*T_*HS_;

    // ---- group 0: Q tiles (hi+lo) ----
    #pragma unroll
    for (int f = 0; f < 8; f++) {
        const int slot = tid + (f << 8);           // 0..2047
        const int row = slot >> 4, c8 = slot & 15;
        const uint32_t off = (uint32_t)((c8 >> 2) * 8192) + tswz(row, c8 & 3);
        const long g = (long)row*HS_ + c8*8;
        CP_A16(sb + FQHI + off, Qhg + g);
        CP_A16(sb + FQLO + off, Qlg + g);
    }
    CP_COMMIT();

    auto load_kv = [&](int kb) {
        const uint32_t st = sb + FKV + (uint32_t)(kb & 1) * KVSTAGE_B;
        const long gb = (long)kb*64*HS_;
        #pragma unroll
        for (int f = 0; f < 4; f++) {
            const int slot = tid + (f << 8);       // 0..1023
            const int row = slot >> 4, c8 = slot & 15;
            const uint32_t off = (uint32_t)((c8 >> 2) * 4096) + tswz(row, c8 & 3);
            const long g = gb + (long)row*HS_ + c8*8;
            CP_A16(st + 0     + off, Khg + g);
            CP_A16(st + 16384 + off, Klg + g);
            CP_A16(st + 32768 + off, Vhg + g);
            CP_A16(st + 49152 + off, Vlg + g);
        }
        CP_COMMIT();
    };

    // ---- adapter tiles (fp32, plain stores) ----
    {
        const float4* AKg = (const float4*)(g_AK + h*AL_*HS_);
        const float4* AVg = (const float4*)(g_AV + h*AL_*HS_);
        for (int i = tid; i < AL_*HS_/4; i += 256) {
            ((float4*)(fsm + FAK))[i] = AKg[i];
            ((float4*)(fsm + FAV))[i] = AVg[i];
        }
    }

    float O[16][4];
    #pragma unroll
    for (int nf = 0; nf < 16; nf++)
        #pragma unroll
        for (int c = 0; c < 4; c++) O[nf][c] = 0.f;
    float m0 = NEG_BIG, m1 = NEG_BIG, l0 = 0.f, l1 = 0.f;
    const float scale = 0.08838834764831843f;

    const int rowg0 = qb*128 + 16*w + rsub;
    const int warp_rmax = qb*128 + 16*w + 15;

    const int kmax = 2*qb + 2;
    load_kv(0);                                   // group 1

    for (int kb = 0; kb < kmax; kb++) {
        if (kb + 1 < kmax) load_kv(kb + 1);
        else CP_COMMIT();
        CP_WAIT(1);
        __syncthreads();

        if (kb*64 <= warp_rmax) {
            const uint32_t kvst = sb + FKV + (uint32_t)(kb & 1) * KVSTAGE_B;

            // ---- S = Q K^T ----
            float S[8][4];
            #pragma unroll
            for (int j = 0; j < 8; j++)
                #pragma unroll
                for (int c = 0; c < 4; c++) S[j][c] = 0.f;

            #pragma unroll
            for (int ks = 0; ks < 8; ks++) {
                const int tQ = ks >> 1, chb = (ks & 1) << 1;
                const int arow = 16*w + (grp & 1)*8 + lr;
                const uint32_t aoff = (uint32_t)(tQ*8192) + tswz(arow, chb + (grp >> 1));
                uint32_t ah[4], al[4];
                LDSM_X4(ah, sb + FQHI + aoff);
                LDSM_X4(al, sb + FQLO + aoff);
                #pragma unroll
                for (int jj = 0; jj < 4; jj++) {
                    const int brow = jj*16 + (grp >> 1)*8 + lr;
                    const uint32_t boff = (uint32_t)(tQ*4096) + tswz(brow, (grp & 1) + chb);
                    uint32_t kh[4], kl[4];
                    LDSM_X4(kh, kvst + 0     + boff);
                    LDSM_X4(kl, kvst + 16384 + boff);
                    #pragma unroll
                    for (int j2 = 0; j2 < 2; j2++) {
                        const int j = jj*2 + j2, jo = j2 << 1;
                        MMA_BF16(S[j], ah, kh[jo], kh[jo+1]);
                        MMA_BF16(S[j], ah, kl[jo], kl[jo+1]);
                        MMA_BF16(S[j], al, kh[jo], kh[jo+1]);
                    }
                }
            }

            // ---- scale + mask ----
            const bool needMask = (kb*64 + 63) > (qb*128 + 16*w);
            #pragma unroll
            for (int j = 0; j < 8; j++)
                #pragma unroll
                for (int c = 0; c < 4; c++) {
                    float sv = S[j][c] * scale;
                    if (needMask) {
                        const int colg = kb*64 + j*8 + 2*lam + (c & 1);
                        const int rowg = rowg0 + ((c >> 1) << 3);
                        if (colg > rowg) sv = NEG_BIG;
                    }
                    S[j][c] = sv;
                }

            // ---- online softmax ----
            float mx0 = S[0][0], mx1 = S[0][2];
            #pragma unroll
            for (int j = 0; j < 8; j++) {
                mx0 = fmaxf(mx0, fmaxf(S[j][0], S[j][1]));
                mx1 = fmaxf(mx1, fmaxf(S[j][2], S[j][3]));
            }
            mx0 = fmaxf(mx0, __shfl_xor_sync(0xffffffffu, mx0, 1));
            mx0 = fmaxf(mx0, __shfl_xor_sync(0xffffffffu, mx0, 2));
            mx1 = fmaxf(mx1, __shfl_xor_sync(0xffffffffu, mx1, 1));
            mx1 = fmaxf(mx1, __shfl_xor_sync(0xffffffffu, mx1, 2));
            const float mn0 = fmaxf(m0, mx0);
            const float mn1 = fmaxf(m1, mx1);
            const float corr0 = __expf(m0 - mn0);
            const float corr1 = __expf(m1 - mn1);
            float rs0 = 0.f, rs1 = 0.f;
            #pragma unroll
            for (int j = 0; j < 8; j++) {
                S[j][0] = __expf(S[j][0] - mn0);
                S[j][1] = __expf(S[j][1] - mn0);
                S[j][2] = __expf(S[j][2] - mn1);
                S[j][3] = __expf(S[j][3] - mn1);
                rs0 += S[j][0] + S[j][1];
                rs1 += S[j][2] + S[j][3];
            }
            l0 = l0*corr0 + rs0;
            l1 = l1*corr1 + rs1;
            m0 = mn0; m1 = mn1;
            #pragma unroll
            for (int nf = 0; nf < 16; nf++) {
                O[nf][0] *= corr0; O[nf][1] *= corr0;
                O[nf][2] *= corr1; O[nf][3] *= corr1;
            }

            // ---- O += P V ----
            #pragma unroll
            for (int ks2 = 0; ks2 < 4; ks2++) {
                const int j0 = 2*ks2, j1 = j0 + 1;
                uint32_t phi[4], plo[4];
                pack2(S[j0][0], S[j0][1], phi[0], plo[0]);
                pack2(S[j0][2], S[j0][3], phi[1], plo[1]);
                pack2(S[j1][0], S[j1][1], phi[2], plo[2]);
                pack2(S[j1][2], S[j1][3], phi[3], plo[3]);
                #pragma unroll
                for (int nc = 0; nc < 8; nc++) {
                    const int vrow = ks2*16 + (grp & 1)*8 + lr;
                    const uint32_t voff = (uint32_t)((nc >> 1) * 4096)
                                        + tswz(vrow, ((nc & 1) << 1) + (grp >> 1));
                    uint32_t vh[4], vl[4];
                    LDSM_X4_T(vh, kvst + 32768 + voff);
                    LDSM_X4_T(vl, kvst + 49152 + voff);
                    MMA_BF16(O[2*nc],   phi, vh[0], vh[1]);
                    MMA_BF16(O[2*nc+1], phi, vh[2], vh[3]);
                    MMA_BF16(O[2*nc],   phi, vl[0], vl[1]);
                    MMA_BF16(O[2*nc+1], phi, vl[2], vl[3]);
                    MMA_BF16(O[2*nc],   plo, vh[0], vh[1]);
                    MMA_BF16(O[2*nc+1], plo, vh[2], vh[3]);
                }
            }
        }
        __syncthreads();
    }

    // ---- finalize l ----
    l0 += __shfl_xor_sync(0xffffffffu, l0, 1);
    l0 += __shfl_xor_sync(0xffffffffu, l0, 2);
    l1 += __shfl_xor_sync(0xffffffffu, l1, 1);
    l1 += __shfl_xor_sync(0xffffffffu, l1, 2);

    // ---- adapter attention (q = hi+lo from smem) ----
    float sa0[AL_], sa1[AL_];
    #pragma unroll
    for (int j = 0; j < AL_; j++) { sa0[j] = 0.f; sa1[j] = 0.f; }
    const float* AKs = (const float*)(fsm + FAK);
    const float* AVs = (const float*)(fsm + FAV);
    #pragma unroll
    for (int rr = 0; rr < 2; rr++) {
        const int rowL = 16*w + rsub + rr*8;
        float* sa = rr ? sa1 : sa0;
        #pragma unroll
        for (int ch = 0; ch < 4; ch++) {
            const uint32_t off = (uint32_t)(lam * 8192) + tswz(rowL, ch);
            uint4 qh = *(const uint4*)(fsm + FQHI + off);
            uint4 ql = *(const uint4*)(fsm + FQLO + off);
            const uint32_t* qhp = (const uint32_t*)&qh;
            const uint32_t* qlp = (const uint32_t*)&ql;
            float q[8];
            #pragma unroll
            for (int e = 0; e < 4; e++) {
                __nv_bfloat162 bh2 = *reinterpret_cast<const __nv_bfloat162*>(&qhp[e]);
                __nv_bfloat162 bl2 = *reinterpret_cast<const __nv_bfloat162*>(&qlp[e]);
                q[2*e]   = __low2float(bh2)  + __low2float(bl2);
                q[2*e+1] = __high2float(bh2) + __high2float(bl2);
            }
            const int d0 = lam*32 + ch*8;
            #pragma unroll
            for (int j = 0; j < AL_; j++) {
                const float* ak = AKs + j*HS_ + d0;
                #pragma unroll
                for (int e = 0; e < 8; e++) sa[j] += q[e] * ak[e];
            }
        }
    }
    #pragma unroll
    for (int j = 0; j < AL_; j++) {
        sa0[j] += __shfl_xor_sync(0xffffffffu, sa0[j], 1);
        sa0[j] += __shfl_xor_sync(0xffffffffu, sa0[j], 2);
        sa1[j] += __shfl_xor_sync(0xffffffffu, sa1[j], 1);
        sa1[j] += __shfl_xor_sync(0xffffffffu, sa1[j], 2);
    }

    const float g = gating[h];
    #pragma unroll
    for (int rr = 0; rr < 2; rr++) {
        float* sa = rr ? sa1 : sa0;
        const float li = rr ? l1 : l0;
        const int rowg = rowg0 + rr*8;
        float mx = sa[0]*scale;
        #pragma unroll
        for (int j = 1; j < AL_; j++) mx = fmaxf(mx, sa[j]*scale);
        float pa[AL_], ssum = 0.f;
        #pragma unroll
        for (int j = 0; j < AL_; j++) { pa[j] = __expf(sa[j]*scale - mx); ssum += pa[j]; }
        const float pg = g / ssum;
        const float inv_l = 1.f / li;
        const long yidx0 = ((long)b*T_ + rowg)*C_ + h*HS_;
        #pragma unroll
        for (int nf = 0; nf < 16; nf++) {
            const int d = nf*8 + 2*lam;
            float o0 = O[nf][rr*2]   * inv_l;
            float o1 = O[nf][rr*2+1] * inv_l;
            #pragma unroll
            for (int j = 0; j < AL_; j++) {
                const float p = pa[j] * pg;
                o0 += p * AVs[j*HS_ + d];
                o1 += p * AVs[j*HS_ + d + 1];
            }
            uint32_t hi, lo; pack2(o0, o1, hi, lo);
            *(uint32_t*)((uint16_t*)g_Yh + yidx0 + d) = hi;
            *(uint32_t*)((uint16_t*)g_Yl + yidx0 + d) = lo;
        }
    }
}

// ======================================================================
extern "C" void kernel_launch(void* const* d_in, const int* in_sizes, int n_in,
                              void* d_out, int out_size)
{
    const float* x      = (const float*)d_in[0];
    const float* rope   = (const float*)d_in[1];
    const float* W_attn = (const float*)d_in[3];
    const float* W_proj = (const float*)d_in[4];
    const float* emb    = (const float*)d_in[5];
    const float* gating = (const float*)d_in[6];
    float* out = (float*)d_out;

    void *xh, *xl, *wah, *wal, *wph, *wpl, *yh, *yl;
    cudaGetSymbolAddress(&xh,  g_xh);  cudaGetSymbolAddress(&xl,  g_xl);
    cudaGetSymbolAddress(&wah, g_wah); cudaGetSymbolAddress(&wal, g_wal);
    cudaGetSymbolAddress(&wph, g_wph); cudaGetSymbolAddress(&wpl, g_wpl);
    cudaGetSymbolAddress(&yh,  g_Yh);  cudaGetSymbolAddress(&yl,  g_Yl);

    cudaFuncSetAttribute(tgemm<0>, cudaFuncAttributeMaxDynamicSharedMemorySize, GEMM_SMEM);
    cudaFuncSetAttribute(tgemm<1>, cudaFuncAttributeMaxDynamicSharedMemorySize, GEMM_SMEM);
    cudaFuncSetAttribute(flash_mma, cudaFuncAttributeMaxDynamicSharedMemorySize, FLASH_SMEM);

    // 0) split inputs into bf16 hi/lo
    {
        int n4;
        n4 = M_ROWS*KDIM/4;
        conv_split<<<(n4+255)/256, 256>>>((const float4*)x, (uint2*)xh, (uint2*)xl, n4);
        n4 = 3*C_*KDIM/4;
        conv_split<<<(n4+255)/256, 256>>>((const float4*)W_attn, (uint2*)wah, (uint2*)wal, n4);
        n4 = C_*KDIM/4;
        conv_split<<<(n4+255)/256, 256>>>((const float4*)W_proj, (uint2*)wph, (uint2*)wpl, n4);
    }
    // 1) QKV GEMM + rope -> split Q/K/V
    tgemm<0><<<dim3(48, 32), 256, GEMM_SMEM>>>(
        (const __nv_bfloat16*)xh, (const __nv_bfloat16*)xl,
        (const __nv_bfloat16*)wah, (const __nv_bfloat16*)wal, rope, nullptr);
    // 2) adapter k/v
    adapter_kv<<<4096, 128>>>(W_attn, emb);
    // 3) flash attention + fused adapter/gating -> split Y
    flash_mma<<<dim3(T_/128, B_*H_), 256, FLASH_SMEM>>>(gating);
    // 4) output projection -> fp32 out
    tgemm<1><<<dim3(16, 32), 256, GEMM_SMEM>>>(
        (const __nv_bfloat16*)yh, (const __nv_bfloat16*)yl,
        (const __nv_bfloat16*)wph, (const __nv_bfloat16*)wpl, nullptr, out);
}

// round 7
// speedup vs baseline: 2.9857x; 1.0003x over previous
#include <cuda_runtime.h>
#include <cuda_bf16.h>
#include <math.h>
#include <stdint.h>

// Problem constants
#define B_ 2
#define T_ 2048
#define C_ 2048
#define H_ 16
#define HS_ 128
#define AL_ 10
#define KDIM 2048
#define M_ROWS 4096

#define NEG_BIG (-1e30f)

// ---------------- scratch: split-bf16 tensors ----------------
#define QKV_ELEMS (B_*H_*T_*HS_)
__device__ __nv_bfloat16 g_Qh[QKV_ELEMS], g_Ql[QKV_ELEMS];
__device__ __nv_bfloat16 g_Kh[QKV_ELEMS], g_Kl[QKV_ELEMS];
__device__ __nv_bfloat16 g_Vh[QKV_ELEMS], g_Vl[QKV_ELEMS];
__device__ __nv_bfloat16 g_Yh[M_ROWS*C_], g_Yl[M_ROWS*C_];
__device__ __nv_bfloat16 g_xh[M_ROWS*KDIM], g_xl[M_ROWS*KDIM];
__device__ __nv_bfloat16 g_wah[3*C_*KDIM], g_wal[3*C_*KDIM];
__device__ __nv_bfloat16 g_wph[C_*KDIM], g_wpl[C_*KDIM];
__device__ float g_AK[H_*AL_*HS_];
__device__ float g_AV[H_*AL_*HS_];

// ======================= helpers =======================
__device__ __forceinline__ uint32_t smem_u32(const void* p) {
    uint32_t a;
    asm("{ .reg .u64 t; cvta.to.shared.u64 t, %1; cvt.u32.u64 %0, t; }" : "=r"(a) : "l"(p));
    return a;
}

#define LDSM_X4(r, addr) \
    asm volatile("ldmatrix.sync.aligned.m8n8.x4.shared.b16 {%0,%1,%2,%3}, [%4];" \
        : "=r"((r)[0]), "=r"((r)[1]), "=r"((r)[2]), "=r"((r)[3]) : "r"(addr))

#define LDSM_X4_T(r, addr) \
    asm volatile("ldmatrix.sync.aligned.m8n8.x4.trans.shared.b16 {%0,%1,%2,%3}, [%4];" \
        : "=r"((r)[0]), "=r"((r)[1]), "=r"((r)[2]), "=r"((r)[3]) : "r"(addr))

#define MMA_BF16(d, a, b0, b1) \
    asm volatile("mma.sync.aligned.m16n8k16.row.col.f32.bf16.bf16.f32 " \
        "{%0,%1,%2,%3}, {%4,%5,%6,%7}, {%8,%9}, {%0,%1,%2,%3};" \
        : "+f"((d)[0]), "+f"((d)[1]), "+f"((d)[2]), "+f"((d)[3]) \
        : "r"((a)[0]), "r"((a)[1]), "r"((a)[2]), "r"((a)[3]), "r"(b0), "r"(b1))

#define CP_A16(dst, src) \
    asm volatile("cp.async.cg.shared.global [%0], [%1], 16;" :: "r"(dst), "l"(src))
#define CP_COMMIT() asm volatile("cp.async.commit_group;")
#define CP_WAIT(n)  asm volatile("cp.async.wait_group %0;" :: "n"(n))

// swizzled byte offset inside a [rows][64B] bf16 tile (4x 16B chunks/row)
__device__ __forceinline__ uint32_t tswz(int row, int chunk) {
    return (uint32_t)(row * 64 + ((chunk ^ ((row >> 1) & 3)) << 4));
}

__device__ __forceinline__ void pack2(float a, float b, uint32_t& hi, uint32_t& lo) {
    __nv_bfloat162 th = __floats2bfloat162_rn(a, b);
    __nv_bfloat162 tl = __floats2bfloat162_rn(a - __low2float(th), b - __high2float(th));
    hi = *reinterpret_cast<uint32_t*>(&th);
    lo = *reinterpret_cast<uint32_t*>(&tl);
}

// ======================================================================
// prep: fp32 -> bf16 hi/lo split (elementwise)
// ======================================================================
__global__ __launch_bounds__(256) void conv_split(
    const float4* __restrict__ src, uint2* __restrict__ hi,
    uint2* __restrict__ lo, int n4)
{
    const int i = blockIdx.x * blockDim.x + threadIdx.x;
    if (i >= n4) return;
    const float4 v = src[i];
    uint32_t h0, l0, h1, l1;
    pack2(v.x, v.y, h0, l0);
    pack2(v.z, v.w, h1, l1);
    hi[i] = make_uint2(h0, h1);
    lo[i] = make_uint2(l0, l1);
}

// ======================================================================
// split-bf16 x3 GEMM (NT), cp.async 3-stage pipeline, KC=64,
// fragment double-buffer (LDSM of ks+1 issued before MMAs of ks).
// MODE 0: rope + pack -> g_{Q,K,V}{h,l}.   MODE 1: fp32 write to Cout.
// ======================================================================
#define KC 64
#define SUB_B 8192
#define STAGE_B 65536
#define NSTAGE 3
#define GEMM_SMEM (NSTAGE*STAGE_B)   // 192 KB

template<int MODE>
__global__ __launch_bounds__(256, 1) void tgemm(
    const __nv_bfloat16* __restrict__ Ah, const __nv_bfloat16* __restrict__ Al,
    const __nv_bfloat16* __restrict__ Bh, const __nv_bfloat16* __restrict__ Bl,
    const float* __restrict__ rope, float* __restrict__ Cout)
{
    extern __shared__ __align__(1024) char smx[];
    const uint32_t sb = smem_u32(smx);

    const int tid  = threadIdx.x;
    const int wid  = tid >> 5;
    const int lane = tid & 31;
    const int wm   = wid & 1;
    const int wn   = wid >> 1;
    const int bm   = blockIdx.y << 7;
    const int bn   = blockIdx.x << 7;

    // load slots: f in 0..3, idx = tid + 256f in [0,1024): row = idx>>3, cq = idx&7
    int lrow[4], lchk[4]; uint32_t lsw[4];
    #pragma unroll
    for (int f = 0; f < 4; f++) {
        int idx = tid + (f << 8);
        lrow[f] = idx >> 3; lchk[f] = idx & 7;
        lsw[f] = (uint32_t)((lchk[f] >> 2) * SUB_B) + tswz(lrow[f], lchk[f] & 3);
    }

    const int grp = lane >> 3, lr = lane & 7;
    uint32_t offA[4][2], offB[2][2];
    #pragma unroll
    for (int i = 0; i < 4; i++)
        #pragma unroll
        for (int ks = 0; ks < 2; ks++) {
            int row = wm*64 + i*16 + (grp & 1)*8 + lr;
            offA[i][ks] = tswz(row, (grp >> 1) + 2*ks);
        }
    #pragma unroll
    for (int jj = 0; jj < 2; jj++)
        #pragma unroll
        for (int ks = 0; ks < 2; ks++) {
            int row = wn*32 + jj*16 + (grp >> 1)*8 + lr;
            offB[jj][ks] = tswz(row, (grp & 1) + 2*ks);
        }

    float acc[4][4][4];
    #pragma unroll
    for (int i = 0; i < 4; i++)
        #pragma unroll
        for (int j = 0; j < 4; j++)
            #pragma unroll
            for (int c = 0; c < 4; c++) acc[i][j][c] = 0.f;

    const __nv_bfloat16* Abh = Ah + (long)bm * KDIM;
    const __nv_bfloat16* Abl = Al + (long)bm * KDIM;
    const __nv_bfloat16* Bbh = Bh + (long)bn * KDIM;
    const __nv_bfloat16* Bbl = Bl + (long)bn * KDIM;

    auto load_stage = [&](int c, int s) {
        const uint32_t st = sb + (uint32_t)s * STAGE_B;
        const long kb = (long)c * KC;
        #pragma unroll
        for (int f = 0; f < 4; f++) {
            const long ga = (long)lrow[f]*KDIM + kb + lchk[f]*8;
            CP_A16(st + 0*16384 + lsw[f], Abh + ga);
            CP_A16(st + 1*16384 + lsw[f], Abl + ga);
            CP_A16(st + 2*16384 + lsw[f], Bbh + ga);
            CP_A16(st + 3*16384 + lsw[f], Bbl + ga);
        }
        CP_COMMIT();
    };

    // fragment double buffers
    uint32_t ah[2][4][4], al[2][4][4], bh[2][2][4], bl[2][2][4];

    auto load_frags = [&](uint32_t stg, int ks, int buf) {
        const int kh2 = ks & 1;
        const uint32_t sub = stg + (uint32_t)((ks >> 1) * SUB_B);
        #pragma unroll
        for (int i = 0; i < 4; i++) {
            LDSM_X4(ah[buf][i], sub + 0*16384 + offA[i][kh2]);
            LDSM_X4(al[buf][i], sub + 1*16384 + offA[i][kh2]);
        }
        #pragma unroll
        for (int jj = 0; jj < 2; jj++) {
            LDSM_X4(bh[buf][jj], sub + 2*16384 + offB[jj][kh2]);
            LDSM_X4(bl[buf][jj], sub + 3*16384 + offB[jj][kh2]);
        }
    };

    auto mma_block = [&](int buf) {
        #pragma unroll
        for (int i = 0; i < 4; i++)
            #pragma unroll
            for (int j = 0; j < 4; j++) {
                const int jj = j >> 1, jo = (j & 1) << 1;
                MMA_BF16(acc[i][j], ah[buf][i], bh[buf][jj][jo], bh[buf][jj][jo+1]);
                MMA_BF16(acc[i][j], ah[buf][i], bl[buf][jj][jo], bl[buf][jj][jo+1]);
                MMA_BF16(acc[i][j], al[buf][i], bh[buf][jj][jo], bh[buf][jj][jo+1]);
            }
    };

    const int NCH = KDIM / KC;     // 32
    load_stage(0, 0);
    load_stage(1, 1);

    for (int c = 0; c < NCH; c++) {
        CP_WAIT(1);
        __syncthreads();

        const uint32_t stg = sb + (uint32_t)(c % NSTAGE) * STAGE_B;
        load_frags(stg, 0, 0);
        #pragma unroll
        for (int ks = 0; ks < 4; ks++) {
            if (ks < 3) load_frags(stg, ks + 1, (ks + 1) & 1);
            mma_block(ks & 1);
        }

        if (c + 2 < NCH) load_stage(c + 2, (c + 2) % NSTAGE);
        else CP_COMMIT();
    }

    // ---------------- epilogue ----------------
    const int lr4 = lane >> 2;
    const int lc2 = (lane & 3) << 1;

    if (MODE == 0) {
        const int sel = bn >> 11;
        const int hh  = (bn & 2047) >> 7;
        __nv_bfloat16* baseH = (sel == 0 ? g_Qh : (sel == 1 ? g_Kh : g_Vh));
        __nv_bfloat16* baseL = (sel == 0 ? g_Ql : (sel == 1 ? g_Kl : g_Vl));
        #pragma unroll
        for (int i = 0; i < 4; i++) {
            #pragma unroll
            for (int j = 0; j < 4; j++) {
                const int d = wn*32 + j*8 + lc2;
                #pragma unroll
                for (int rh = 0; rh < 2; rh++) {
                    const int m = bm + wm*64 + i*16 + lr4 + rh*8;
                    const int b = m >> 11, t = m & 2047;
                    float v0 = acc[i][j][rh*2], v1 = acc[i][j][rh*2+1];
                    if (sel < 2) {
                        const float2 rr = *(const float2*)(rope + (long)t*128 + d);
                        const float o0 = v0*rr.x - v1*rr.y;
                        const float o1 = v1*rr.x + v0*rr.y;
                        v0 = o0; v1 = o1;
                    }
                    uint32_t hi, lo; pack2(v0, v1, hi, lo);
                    const long idx = ((long)(b*H_ + hh)*T_ + t)*HS_ + d;
                    *(uint32_t*)((uint16_t*)baseH + idx) = hi;
                    *(uint32_t*)((uint16_t*)baseL + idx) = lo;
                }
            }
        }
    } else {
        #pragma unroll
        for (int i = 0; i < 4; i++)
            #pragma unroll
            for (int j = 0; j < 4; j++) {
                const int ncol = bn + wn*32 + j*8 + lc2;
                #pragma unroll
                for (int rh = 0; rh < 2; rh++) {
                    const int m = bm + wm*64 + i*16 + lr4 + rh*8;
                    *(float2*)(Cout + (long)m*C_ + ncol) =
                        make_float2(acc[i][j][rh*2], acc[i][j][rh*2+1]);
                }
            }
    }
}

// ======================================================================
// Adapter K/V (unchanged; fp32)
// ======================================================================
__global__ __launch_bounds__(128) void adapter_kv(
    const float* __restrict__ W, const float* __restrict__ emb)
{
    const int bx = blockIdx.x;
    const int np = 2048 + bx;
    const float* wrow = W + (long)np * KDIM;

    float part[AL_] = {};
    for (int k = threadIdx.x; k < KDIM; k += 128) {
        float w = wrow[k];
        #pragma unroll
        for (int j = 0; j < AL_; j++) part[j] += w * emb[j*KDIM + k];
    }
    #pragma unroll
    for (int j = 0; j < AL_; j++)
        #pragma unroll
        for (int off = 16; off; off >>= 1)
            part[j] += __shfl_xor_sync(0xffffffffu, part[j], off);

    __shared__ float red[AL_][4];
    const int w = threadIdx.x >> 5, lane = threadIdx.x & 31;
    if (lane == 0)
        #pragma unroll
        for (int j = 0; j < AL_; j++) red[j][w] = part[j];
    __syncthreads();
    if (threadIdx.x < AL_) {
        const int j = threadIdx.x;
        float s = red[j][0] + red[j][1] + red[j][2] + red[j][3];
        const int isv = bx >> 11;
        const int nn  = bx & 2047;
        const int h   = nn >> 7, d = nn & 127;
        float* dst = isv ? g_AV : g_AK;
        dst[(h*AL_ + j)*HS_ + d] = s;
    }
}

// ======================================================================
// Flash attention (split-bf16 x3 tensor cores), cp.async loads of
// pre-split Q/K/V, 2-stage KV pipeline, fused adapter + gating.
// BM=128, BN=64, 8 warps.  (unchanged from round 5/6)
// ======================================================================
#define FQHI 0
#define FQLO 32768
#define FKV  65536
#define KVSTAGE_B 65536          // Kh,Kl,Vh,Vl x 16KB
#define FAK  (FKV + 2*KVSTAGE_B)             // 196608
#define FAV  (FAK + AL_*HS_*4)               // 201728
#define FLASH_SMEM (FAV + AL_*HS_*4)         // 206848

__global__ __launch_bounds__(256, 1) void flash_mma(const float* __restrict__ gating)
{
    extern __shared__ __align__(1024) char fsm[];
    const uint32_t sb = smem_u32(fsm);

    const int tid  = threadIdx.x;
    const int w    = tid >> 5;
    const int lane = tid & 31;
    const int grp  = lane >> 3, lr = lane & 7;
    const int lam  = lane & 3;
    const int rsub = lane >> 2;

    const int qb = (gridDim.x - 1) - blockIdx.x;
    const int bhI = blockIdx.y;
    const int h  = bhI & 15;
    const int b  = bhI >> 4;

    const __nv_bfloat16* Qhg = g_Qh + (long)bhI*T_*HS_ + (long)qb*128*HS_;
    const __nv_bfloat16* Qlg = g_Ql + (long)bhI*T_*HS_ + (long)qb*128*HS_;
    const __nv_bfloat16* Khg = g_Kh + (long)bhI*T_*HS_;
    const __nv_bfloat16* Klg = g_Kl + (long)bhI*T_*HS_;
    const __nv_bfloat16* Vhg = g_Vh + (long)bhI*T_*HS_;
    const __nv_bfloat16* Vlg = g_Vl + (long)bhI*T_*HS_;

    // ---- group 0: Q tiles (hi+lo) ----
    #pragma unroll
    for (int f = 0; f < 8; f++) {
        const int slot = tid + (f << 8);           // 0..2047
        const int row = slot >> 4, c8 = slot & 15;
        const uint32_t off = (uint32_t)((c8 >> 2) * 8192) + tswz(row, c8 & 3);
        const long g = (long)row*HS_ + c8*8;
        CP_A16(sb + FQHI + off, Qhg + g);
        CP_A16(sb + FQLO + off, Qlg + g);
    }
    CP_COMMIT();

    auto load_kv = [&](int kb) {
        const uint32_t st = sb + FKV + (uint32_t)(kb & 1) * KVSTAGE_B;
        const long gb = (long)kb*64*HS_;
        #pragma unroll
        for (int f = 0; f < 4; f++) {
            const int slot = tid + (f << 8);       // 0..1023
            const int row = slot >> 4, c8 = slot & 15;
            const uint32_t off = (uint32_t)((c8 >> 2) * 4096) + tswz(row, c8 & 3);
            const long g = gb + (long)row*HS_ + c8*8;
            CP_A16(st + 0     + off, Khg + g);
            CP_A16(st + 16384 + off, Klg + g);
            CP_A16(st + 32768 + off, Vhg + g);
            CP_A16(st + 49152 + off, Vlg + g);
        }
        CP_COMMIT();
    };

    // ---- adapter tiles (fp32, plain stores) ----
    {
        const float4* AKg = (const float4*)(g_AK + h*AL_*HS_);
        const float4* AVg = (const float4*)(g_AV + h*AL_*HS_);
        for (int i = tid; i < AL_*HS_/4; i += 256) {
            ((float4*)(fsm + FAK))[i] = AKg[i];
            ((float4*)(fsm + FAV))[i] = AVg[i];
        }
    }

    float O[16][4];
    #pragma unroll
    for (int nf = 0; nf < 16; nf++)
        #pragma unroll
        for (int c = 0; c < 4; c++) O[nf][c] = 0.f;
    float m0 = NEG_BIG, m1 = NEG_BIG, l0 = 0.f, l1 = 0.f;
    const float scale = 0.08838834764831843f;

    const int rowg0 = qb*128 + 16*w + rsub;
    const int warp_rmax = qb*128 + 16*w + 15;

    const int kmax = 2*qb + 2;
    load_kv(0);                                   // group 1

    for (int kb = 0; kb < kmax; kb++) {
        if (kb + 1 < kmax) load_kv(kb + 1);
        else CP_COMMIT();
        CP_WAIT(1);
        __syncthreads();

        if (kb*64 <= warp_rmax) {
            const uint32_t kvst = sb + FKV + (uint32_t)(kb & 1) * KVSTAGE_B;

            // ---- S = Q K^T ----
            float S[8][4];
            #pragma unroll
            for (int j = 0; j < 8; j++)
                #pragma unroll
                for (int c = 0; c < 4; c++) S[j][c] = 0.f;

            #pragma unroll
            for (int ks = 0; ks < 8; ks++) {
                const int tQ = ks >> 1, chb = (ks & 1) << 1;
                const int arow = 16*w + (grp & 1)*8 + lr;
                const uint32_t aoff = (uint32_t)(tQ*8192) + tswz(arow, chb + (grp >> 1));
                uint32_t ah[4], al[4];
                LDSM_X4(ah, sb + FQHI + aoff);
                LDSM_X4(al, sb + FQLO + aoff);
                #pragma unroll
                for (int jj = 0; jj < 4; jj++) {
                    const int brow = jj*16 + (grp >> 1)*8 + lr;
                    const uint32_t boff = (uint32_t)(tQ*4096) + tswz(brow, (grp & 1) + chb);
                    uint32_t kh[4], kl[4];
                    LDSM_X4(kh, kvst + 0     + boff);
                    LDSM_X4(kl, kvst + 16384 + boff);
                    #pragma unroll
                    for (int j2 = 0; j2 < 2; j2++) {
                        const int j = jj*2 + j2, jo = j2 << 1;
                        MMA_BF16(S[j], ah, kh[jo], kh[jo+1]);
                        MMA_BF16(S[j], ah, kl[jo], kl[jo+1]);
                        MMA_BF16(S[j], al, kh[jo], kh[jo+1]);
                    }
                }
            }

            // ---- scale + mask ----
            const bool needMask = (kb*64 + 63) > (qb*128 + 16*w);
            #pragma unroll
            for (int j = 0; j < 8; j++)
                #pragma unroll
                for (int c = 0; c < 4; c++) {
                    float sv = S[j][c] * scale;
                    if (needMask) {
                        const int colg = kb*64 + j*8 + 2*lam + (c & 1);
                        const int rowg = rowg0 + ((c >> 1) << 3);
                        if (colg > rowg) sv = NEG_BIG;
                    }
                    S[j][c] = sv;
                }

            // ---- online softmax ----
            float mx0 = S[0][0], mx1 = S[0][2];
            #pragma unroll
            for (int j = 0; j < 8; j++) {
                mx0 = fmaxf(mx0, fmaxf(S[j][0], S[j][1]));
                mx1 = fmaxf(mx1, fmaxf(S[j][2], S[j][3]));
            }
            mx0 = fmaxf(mx0, __shfl_xor_sync(0xffffffffu, mx0, 1));
            mx0 = fmaxf(mx0, __shfl_xor_sync(0xffffffffu, mx0, 2));
            mx1 = fmaxf(mx1, __shfl_xor_sync(0xffffffffu, mx1, 1));
            mx1 = fmaxf(mx1, __shfl_xor_sync(0xffffffffu, mx1, 2));
            const float mn0 = fmaxf(m0, mx0);
            const float mn1 = fmaxf(m1, mx1);
            const float corr0 = __expf(m0 - mn0);
            const float corr1 = __expf(m1 - mn1);
            float rs0 = 0.f, rs1 = 0.f;
            #pragma unroll
            for (int j = 0; j < 8; j++) {
                S[j][0] = __expf(S[j][0] - mn0);
                S[j][1] = __expf(S[j][1] - mn0);
                S[j][2] = __expf(S[j][2] - mn1);
                S[j][3] = __expf(S[j][3] - mn1);
                rs0 += S[j][0] + S[j][1];
                rs1 += S[j][2] + S[j][3];
            }
            l0 = l0*corr0 + rs0;
            l1 = l1*corr1 + rs1;
            m0 = mn0; m1 = mn1;
            #pragma unroll
            for (int nf = 0; nf < 16; nf++) {
                O[nf][0] *= corr0; O[nf][1] *= corr0;
                O[nf][2] *= corr1; O[nf][3] *= corr1;
            }

            // ---- O += P V ----
            #pragma unroll
            for (int ks2 = 0; ks2 < 4; ks2++) {
                const int j0 = 2*ks2, j1 = j0 + 1;
                uint32_t phi[4], plo[4];
                pack2(S[j0][0], S[j0][1], phi[0], plo[0]);
                pack2(S[j0][2], S[j0][3], phi[1], plo[1]);
                pack2(S[j1][0], S[j1][1], phi[2], plo[2]);
                pack2(S[j1][2], S[j1][3], phi[3], plo[3]);
                #pragma unroll
                for (int nc = 0; nc < 8; nc++) {
                    const int vrow = ks2*16 + (grp & 1)*8 + lr;
                    const uint32_t voff = (uint32_t)((nc >> 1) * 4096)
                                        + tswz(vrow, ((nc & 1) << 1) + (grp >> 1));
                    uint32_t vh[4], vl[4];
                    LDSM_X4_T(vh, kvst + 32768 + voff);
                    LDSM_X4_T(vl, kvst + 49152 + voff);
                    MMA_BF16(O[2*nc],   phi, vh[0], vh[1]);
                    MMA_BF16(O[2*nc+1], phi, vh[2], vh[3]);
                    MMA_BF16(O[2*nc],   phi, vl[0], vl[1]);
                    MMA_BF16(O[2*nc+1], phi, vl[2], vl[3]);
                    MMA_BF16(O[2*nc],   plo, vh[0], vh[1]);
                    MMA_BF16(O[2*nc+1], plo, vh[2], vh[3]);
                }
            }
        }
        __syncthreads();
    }

    // ---- finalize l ----
    l0 += __shfl_xor_sync(0xffffffffu, l0, 1);
    l0 += __shfl_xor_sync(0xffffffffu, l0, 2);
    l1 += __shfl_xor_sync(0xffffffffu, l1, 1);
    l1 += __shfl_xor_sync(0xffffffffu, l1, 2);

    // ---- adapter attention (q = hi+lo from smem) ----
    float sa0[AL_], sa1[AL_];
    #pragma unroll
    for (int j = 0; j < AL_; j++) { sa0[j] = 0.f; sa1[j] = 0.f; }
    const float* AKs = (const float*)(fsm + FAK);
    const float* AVs = (const float*)(fsm + FAV);
    #pragma unroll
    for (int rr = 0; rr < 2; rr++) {
        const int rowL = 16*w + rsub + rr*8;
        float* sa = rr ? sa1 : sa0;
        #pragma unroll
        for (int ch = 0; ch < 4; ch++) {
            const uint32_t off = (uint32_t)(lam * 8192) + tswz(rowL, ch);
            uint4 qh = *(const uint4*)(fsm + FQHI + off);
            uint4 ql = *(const uint4*)(fsm + FQLO + off);
            const uint32_t* qhp = (const uint32_t*)&qh;
            const uint32_t* qlp = (const uint32_t*)&ql;
            float q[8];
            #pragma unroll
            for (int e = 0; e < 4; e++) {
                __nv_bfloat162 bh2 = *reinterpret_cast<const __nv_bfloat162*>(&qhp[e]);
                __nv_bfloat162 bl2 = *reinterpret_cast<const __nv_bfloat162*>(&qlp[e]);
                q[2*e]   = __low2float(bh2)  + __low2float(bl2);
                q[2*e+1] = __high2float(bh2) + __high2float(bl2);
            }
            const int d0 = lam*32 + ch*8;
            #pragma unroll
            for (int j = 0; j < AL_; j++) {
                const float* ak = AKs + j*HS_ + d0;
                #pragma unroll
                for (int e = 0; e < 8; e++) sa[j] += q[e] * ak[e];
            }
        }
    }
    #pragma unroll
    for (int j = 0; j < AL_; j++) {
        sa0[j] += __shfl_xor_sync(0xffffffffu, sa0[j], 1);
        sa0[j] += __shfl_xor_sync(0xffffffffu, sa0[j], 2);
        sa1[j] += __shfl_xor_sync(0xffffffffu, sa1[j], 1);
        sa1[j] += __shfl_xor_sync(0xffffffffu, sa1[j], 2);
    }

    const float g = gating[h];
    #pragma unroll
    for (int rr = 0; rr < 2; rr++) {
        float* sa = rr ? sa1 : sa0;
        const float li = rr ? l1 : l0;
        const int rowg = rowg0 + rr*8;
        float mx = sa[0]*scale;
        #pragma unroll
        for (int j = 1; j < AL_; j++) mx = fmaxf(mx, sa[j]*scale);
        float pa[AL_], ssum = 0.f;
        #pragma unroll
        for (int j = 0; j < AL_; j++) { pa[j] = __expf(sa[j]*scale - mx); ssum += pa[j]; }
        const float pg = g / ssum;
        const float inv_l = 1.f / li;
        const long yidx0 = ((long)b*T_ + rowg)*C_ + h*HS_;
        #pragma unroll
        for (int nf = 0; nf < 16; nf++) {
            const int d = nf*8 + 2*lam;
            float o0 = O[nf][rr*2]   * inv_l;
            float o1 = O[nf][rr*2+1] * inv_l;
            #pragma unroll
            for (int j = 0; j < AL_; j++) {
                const float p = pa[j] * pg;
                o0 += p * AVs[j*HS_ + d];
                o1 += p * AVs[j*HS_ + d + 1];
            }
            uint32_t hi, lo; pack2(o0, o1, hi, lo);
            *(uint32_t*)((uint16_t*)g_Yh + yidx0 + d) = hi;
            *(uint32_t*)((uint16_t*)g_Yl + yidx0 + d) = lo;
        }
    }
}

// ======================================================================
extern "C" void kernel_launch(void* const* d_in, const int* in_sizes, int n_in,
                              void* d_out, int out_size)
{
    const float* x      = (const float*)d_in[0];
    const float* rope   = (const float*)d_in[1];
    const float* W_attn = (const float*)d_in[3];
    const float* W_proj = (const float*)d_in[4];
    const float* emb    = (const float*)d_in[5];
    const float* gating = (const float*)d_in[6];
    float* out = (float*)d_out;

    void *xh, *xl, *wah, *wal, *wph, *wpl, *yh, *yl;
    cudaGetSymbolAddress(&xh,  g_xh);  cudaGetSymbolAddress(&xl,  g_xl);
    cudaGetSymbolAddress(&wah, g_wah); cudaGetSymbolAddress(&wal, g_wal);
    cudaGetSymbolAddress(&wph, g_wph); cudaGetSymbolAddress(&wpl, g_wpl);
    cudaGetSymbolAddress(&yh,  g_Yh);  cudaGetSymbolAddress(&yl,  g_Yl);

    cudaFuncSetAttribute(tgemm<0>, cudaFuncAttributeMaxDynamicSharedMemorySize, GEMM_SMEM);
    cudaFuncSetAttribute(tgemm<1>, cudaFuncAttributeMaxDynamicSharedMemorySize, GEMM_SMEM);
    cudaFuncSetAttribute(flash_mma, cudaFuncAttributeMaxDynamicSharedMemorySize, FLASH_SMEM);

    // 0) split inputs into bf16 hi/lo
    {
        int n4;
        n4 = M_ROWS*KDIM/4;
        conv_split<<<(n4+255)/256, 256>>>((const float4*)x, (uint2*)xh, (uint2*)xl, n4);
        n4 = 3*C_*KDIM/4;
        conv_split<<<(n4+255)/256, 256>>>((const float4*)W_attn, (uint2*)wah, (uint2*)wal, n4);
        n4 = C_*KDIM/4;
        conv_split<<<(n4+255)/256, 256>>>((const float4*)W_proj, (uint2*)wph, (uint2*)wpl, n4);
    }
    // 1) QKV GEMM + rope -> split Q/K/V
    tgemm<0><<<dim3(48, 32), 256, GEMM_SMEM>>>(
        (const __nv_bfloat16*)xh, (const __nv_bfloat16*)xl,
        (const __nv_bfloat16*)wah, (const __nv_bfloat16*)wal, rope, nullptr);
    // 2) adapter k/v
    adapter_kv<<<4096, 128>>>(W_attn, emb);
    // 3) flash attention + fused adapter/gating -> split Y
    flash_mma<<<dim3(T_/128, B_*H_), 256, FLASH_SMEM>>>(gating);
    // 4) output projection -> fp32 out
    tgemm<1><<<dim3(16, 32), 256, GEMM_SMEM>>>(
        (const __nv_bfloat16*)yh, (const __nv_bfloat16*)yl,
        (const __nv_bfloat16*)wph, (const __nv_bfloat16*)wpl, nullptr, out);
}

// round 9
// speedup vs baseline: 3.1807x; 1.0653x over previous
#include <cuda_runtime.h>
#include <cuda_bf16.h>
#include <math.h>
#include <stdint.h>

// Problem constants
#define B_ 2
#define T_ 2048
#define C_ 2048
#define H_ 16
#define HS_ 128
#define AL_ 10
#define KDIM 2048
#define M_ROWS 4096

#define NEG_BIG (-1e30f)

// ---------------- scratch: split-bf16 tensors ----------------
#define QKV_ELEMS (B_*H_*T_*HS_)
__device__ __nv_bfloat16 g_Qh[QKV_ELEMS], g_Ql[QKV_ELEMS];
__device__ __nv_bfloat16 g_Kh[QKV_ELEMS], g_Kl[QKV_ELEMS];
__device__ __nv_bfloat16 g_Vh[QKV_ELEMS], g_Vl[QKV_ELEMS];
__device__ __nv_bfloat16 g_Yh[M_ROWS*C_], g_Yl[M_ROWS*C_];
__device__ __nv_bfloat16 g_xh[M_ROWS*KDIM], g_xl[M_ROWS*KDIM];
__device__ __nv_bfloat16 g_wah[3*C_*KDIM], g_wal[3*C_*KDIM];
__device__ __nv_bfloat16 g_wph[C_*KDIM], g_wpl[C_*KDIM];
__device__ float g_AK[H_*AL_*HS_];
__device__ float g_AV[H_*AL_*HS_];

// ======================= helpers =======================
__device__ __forceinline__ uint32_t smem_u32(const void* p) {
    uint32_t a;
    asm("{ .reg .u64 t; cvta.to.shared.u64 t, %1; cvt.u32.u64 %0, t; }" : "=r"(a) : "l"(p));
    return a;
}

#define LDSM_X4(r, addr) \
    asm volatile("ldmatrix.sync.aligned.m8n8.x4.shared.b16 {%0,%1,%2,%3}, [%4];" \
        : "=r"((r)[0]), "=r"((r)[1]), "=r"((r)[2]), "=r"((r)[3]) : "r"(addr))

#define LDSM_X4_T(r, addr) \
    asm volatile("ldmatrix.sync.aligned.m8n8.x4.trans.shared.b16 {%0,%1,%2,%3}, [%4];" \
        : "=r"((r)[0]), "=r"((r)[1]), "=r"((r)[2]), "=r"((r)[3]) : "r"(addr))

#define MMA_BF16(d, a, b0, b1) \
    asm volatile("mma.sync.aligned.m16n8k16.row.col.f32.bf16.bf16.f32 " \
        "{%0,%1,%2,%3}, {%4,%5,%6,%7}, {%8,%9}, {%0,%1,%2,%3};" \
        : "+f"((d)[0]), "+f"((d)[1]), "+f"((d)[2]), "+f"((d)[3]) \
        : "r"((a)[0]), "r"((a)[1]), "r"((a)[2]), "r"((a)[3]), "r"(b0), "r"(b1))

#define CP_A16(dst, src) \
    asm volatile("cp.async.cg.shared.global [%0], [%1], 16;" :: "r"(dst), "l"(src))
#define CP_COMMIT() asm volatile("cp.async.commit_group;")
#define CP_WAIT(n)  asm volatile("cp.async.wait_group %0;" :: "n"(n))

// swizzled byte offset inside a [rows][64B] bf16 tile (4x 16B chunks/row)
__device__ __forceinline__ uint32_t tswz(int row, int chunk) {
    return (uint32_t)(row * 64 + ((chunk ^ ((row >> 1) & 3)) << 4));
}

__device__ __forceinline__ void pack2(float a, float b, uint32_t& hi, uint32_t& lo) {
    __nv_bfloat162 th = __floats2bfloat162_rn(a, b);
    __nv_bfloat162 tl = __floats2bfloat162_rn(a - __low2float(th), b - __high2float(th));
    hi = *reinterpret_cast<uint32_t*>(&th);
    lo = *reinterpret_cast<uint32_t*>(&tl);
}

// ======================================================================
// prep: fp32 -> bf16 hi/lo split (elementwise)
// ======================================================================
__global__ __launch_bounds__(256) void conv_split(
    const float4* __restrict__ src, uint2* __restrict__ hi,
    uint2* __restrict__ lo, int n4)
{
    const int i = blockIdx.x * blockDim.x + threadIdx.x;
    if (i >= n4) return;
    const float4 v = src[i];
    uint32_t h0, l0, h1, l1;
    pack2(v.x, v.y, h0, l0);
    pack2(v.z, v.w, h1, l1);
    hi[i] = make_uint2(h0, h1);
    lo[i] = make_uint2(l0, l1);
}

// ======================================================================
// split-bf16 x3 GEMM (NT): CTA 128x128, 4 warps of 64x64, KC=32,
// 3-stage cp.async pipeline, 2 CTAs/SM.
// Stage (32KB): Ah[8K] Al[8K] Bh[8K] Bl[8K], each 128 rows x 64B swizzled.
// MODE 0: rope + pack -> g_{Q,K,V}{h,l}.   MODE 1: fp32 write to Cout.
// ======================================================================
#define KC 32
#define STAGE_B 32768
#define NSTAGE 3
#define GEMM_SMEM (NSTAGE*STAGE_B)   // 96 KB -> 2 CTAs/SM

template<int MODE>
__global__ __launch_bounds__(128, 2) void tgemm(
    const __nv_bfloat16* __restrict__ Ah, const __nv_bfloat16* __restrict__ Al,
    const __nv_bfloat16* __restrict__ Bh, const __nv_bfloat16* __restrict__ Bl,
    const float* __restrict__ rope, float* __restrict__ Cout)
{
    extern __shared__ __align__(1024) char smx[];
    const uint32_t sb = smem_u32(smx);

    const int tid  = threadIdx.x;
    const int wid  = tid >> 5;
    const int lane = tid & 31;
    const int wm   = wid & 1;        // 64-row half
    const int wn   = wid >> 1;       // 64-col half
    const int bm   = blockIdx.y << 7;
    const int bn   = blockIdx.x << 7;

    // load slots: f in 0..3, idx = tid + 128f in [0,512): row = idx>>2, chunk = idx&3
    int lrow[4], lchk[4]; uint32_t lsw[4];
    #pragma unroll
    for (int f = 0; f < 4; f++) {
        int idx = tid + (f << 7);
        lrow[f] = idx >> 2; lchk[f] = idx & 3;
        lsw[f] = tswz(lrow[f], lchk[f]);
    }

    const int grp = lane >> 3, lr = lane & 7;
    uint32_t offA[4][2], offB[4][2];
    #pragma unroll
    for (int i = 0; i < 4; i++)
        #pragma unroll
        for (int ks = 0; ks < 2; ks++) {
            int row = wm*64 + i*16 + (grp & 1)*8 + lr;
            offA[i][ks] = tswz(row, (grp >> 1) + 2*ks);
        }
    #pragma unroll
    for (int jj = 0; jj < 4; jj++)
        #pragma unroll
        for (int ks = 0; ks < 2; ks++) {
            int row = wn*64 + jj*16 + (grp >> 1)*8 + lr;
            offB[jj][ks] = tswz(row, (grp & 1) + 2*ks);
        }

    float acc[4][8][4];
    #pragma unroll
    for (int i = 0; i < 4; i++)
        #pragma unroll
        for (int j = 0; j < 8; j++)
            #pragma unroll
            for (int c = 0; c < 4; c++) acc[i][j][c] = 0.f;

    const __nv_bfloat16* Abh = Ah + (long)bm * KDIM;
    const __nv_bfloat16* Abl = Al + (long)bm * KDIM;
    const __nv_bfloat16* Bbh = Bh + (long)bn * KDIM;
    const __nv_bfloat16* Bbl = Bl + (long)bn * KDIM;

    auto load_stage = [&](int c, int s) {
        const uint32_t st = sb + (uint32_t)s * STAGE_B;
        const long kb = (long)c * KC;
        #pragma unroll
        for (int f = 0; f < 4; f++) {
            const long ga = (long)lrow[f]*KDIM + kb + lchk[f]*8;
            CP_A16(st + 0*8192 + lsw[f], Abh + ga);
            CP_A16(st + 1*8192 + lsw[f], Abl + ga);
            CP_A16(st + 2*8192 + lsw[f], Bbh + ga);
            CP_A16(st + 3*8192 + lsw[f], Bbl + ga);
        }
        CP_COMMIT();
    };

    const int NCH = KDIM / KC;     // 64
    load_stage(0, 0);
    load_stage(1, 1);

    for (int c = 0; c < NCH; c++) {
        CP_WAIT(1);
        __syncthreads();

        const uint32_t stg = sb + (uint32_t)(c % NSTAGE) * STAGE_B;
        #pragma unroll
        for (int ks = 0; ks < 2; ks++) {
            uint32_t ah[4][4], al[4][4], bh[4][4], bl[4][4];
            #pragma unroll
            for (int i = 0; i < 4; i++) {
                LDSM_X4(ah[i], stg + 0*8192 + offA[i][ks]);
                LDSM_X4(al[i], stg + 1*8192 + offA[i][ks]);
            }
            #pragma unroll
            for (int jj = 0; jj < 4; jj++) {
                LDSM_X4(bh[jj], stg + 2*8192 + offB[jj][ks]);
                LDSM_X4(bl[jj], stg + 3*8192 + offB[jj][ks]);
            }
            #pragma unroll
            for (int i = 0; i < 4; i++)
                #pragma unroll
                for (int j = 0; j < 8; j++) {
                    const int jj = j >> 1, jo = (j & 1) << 1;
                    MMA_BF16(acc[i][j], ah[i], bh[jj][jo], bh[jj][jo+1]);
                    MMA_BF16(acc[i][j], ah[i], bl[jj][jo], bl[jj][jo+1]);
                    MMA_BF16(acc[i][j], al[i], bh[jj][jo], bh[jj][jo+1]);
                }
        }

        if (c + 2 < NCH) load_stage(c + 2, (c + 2) % NSTAGE);
        else CP_COMMIT();
    }

    // ---------------- epilogue ----------------
    const int lr4 = lane >> 2;
    const int lc2 = (lane & 3) << 1;

    if (MODE == 0) {
        const int sel = bn >> 11;
        const int hh  = (bn & 2047) >> 7;
        __nv_bfloat16* baseH = (sel == 0 ? g_Qh : (sel == 1 ? g_Kh : g_Vh));
        __nv_bfloat16* baseL = (sel == 0 ? g_Ql : (sel == 1 ? g_Kl : g_Vl));
        #pragma unroll
        for (int i = 0; i < 4; i++) {
            #pragma unroll
            for (int j = 0; j < 8; j++) {
                const int d = wn*64 + j*8 + lc2;
                #pragma unroll
                for (int rh = 0; rh < 2; rh++) {
                    const int m = bm + wm*64 + i*16 + lr4 + rh*8;
                    const int b = m >> 11, t = m & 2047;
                    float v0 = acc[i][j][rh*2], v1 = acc[i][j][rh*2+1];
                    if (sel < 2) {
                        const float2 rr = *(const float2*)(rope + (long)t*128 + d);
                        const float o0 = v0*rr.x - v1*rr.y;
                        const float o1 = v1*rr.x + v0*rr.y;
                        v0 = o0; v1 = o1;
                    }
                    uint32_t hi, lo; pack2(v0, v1, hi, lo);
                    const long idx = ((long)(b*H_ + hh)*T_ + t)*HS_ + d;
                    *(uint32_t*)((uint16_t*)baseH + idx) = hi;
                    *(uint32_t*)((uint16_t*)baseL + idx) = lo;
                }
            }
        }
    } else {
        #pragma unroll
        for (int i = 0; i < 4; i++)
            #pragma unroll
            for (int j = 0; j < 8; j++) {
                const int ncol = bn + wn*64 + j*8 + lc2;
                #pragma unroll
                for (int rh = 0; rh < 2; rh++) {
                    const int m = bm + wm*64 + i*16 + lr4 + rh*8;
                    *(float2*)(Cout + (long)m*C_ + ncol) =
                        make_float2(acc[i][j][rh*2], acc[i][j][rh*2+1]);
                }
            }
    }
}

// ======================================================================
// Adapter K/V (unchanged; fp32)
// ======================================================================
__global__ __launch_bounds__(128) void adapter_kv(
    const float* __restrict__ W, const float* __restrict__ emb)
{
    const int bx = blockIdx.x;
    const int np = 2048 + bx;
    const float* wrow = W + (long)np * KDIM;

    float part[AL_] = {};
    for (int k = threadIdx.x; k < KDIM; k += 128) {
        float w = wrow[k];
        #pragma unroll
        for (int j = 0; j < AL_; j++) part[j] += w * emb[j*KDIM + k];
    }
    #pragma unroll
    for (int j = 0; j < AL_; j++)
        #pragma unroll
        for (int off = 16; off; off >>= 1)
            part[j] += __shfl_xor_sync(0xffffffffu, part[j], off);

    __shared__ float red[AL_][4];
    const int w = threadIdx.x >> 5, lane = threadIdx.x & 31;
    if (lane == 0)
        #pragma unroll
        for (int j = 0; j < AL_; j++) red[j][w] = part[j];
    __syncthreads();
    if (threadIdx.x < AL_) {
        const int j = threadIdx.x;
        float s = red[j][0] + red[j][1] + red[j][2] + red[j][3];
        const int isv = bx >> 11;
        const int nn  = bx & 2047;
        const int h   = nn >> 7, d = nn & 127;
        float* dst = isv ? g_AV : g_AK;
        dst[(h*AL_ + j)*HS_ + d] = s;
    }
}

// ======================================================================
// Flash attention (split-bf16 x3 tensor cores), cp.async loads of
// pre-split Q/K/V, 2-stage KV pipeline, fused adapter + gating.
// BM=128, BN=64, 8 warps.  (unchanged)
// ======================================================================
#define FQHI 0
#define FQLO 32768
#define FKV  65536
#define KVSTAGE_B 65536          // Kh,Kl,Vh,Vl x 16KB
#define FAK  (FKV + 2*KVSTAGE_B)             // 196608
#define FAV  (FAK + AL_*HS_*4)               // 201728
#define FLASH_SMEM (FAV + AL_*HS_*4)         // 206848

__global__ __launch_bounds__(256, 1) void flash_mma(const float* __restrict__ gating)
{
    extern __shared__ __align__(1024) char fsm[];
    const uint32_t sb = smem_u32(fsm);

    const int tid  = threadIdx.x;
    const int w    = tid >> 5;
    const int lane = tid & 31;
    const int grp  = lane >> 3, lr = lane & 7;
    const int lam  = lane & 3;
    const int rsub = lane >> 2;

    const int qb = (gridDim.x - 1) - blockIdx.x;
    const int bhI = blockIdx.y;
    const int h  = bhI & 15;
    const int b  = bhI >> 4;

    const __nv_bfloat16* Qhg = g_Qh + (long)bhI*T_*HS_ + (long)qb*128*HS_;
    const __nv_bfloat16* Qlg = g_Ql + (long)bhI*T_*HS_ + (long)qb*128*HS_;
    const __nv_bfloat16* Khg = g_Kh + (long)bhI*T_*HS_;
    const __nv_bfloat16* Klg = g_Kl + (long)bhI*T_*HS_;
    const __nv_bfloat16* Vhg = g_Vh + (long)bhI*T_*HS_;
    const __nv_bfloat16* Vlg = g_Vl + (long)bhI*T_*HS_;

    // ---- group 0: Q tiles (hi+lo) ----
    #pragma unroll
    for (int f = 0; f < 8; f++) {
        const int slot = tid + (f << 8);           // 0..2047
        const int row = slot >> 4, c8 = slot & 15;
        const uint32_t off = (uint32_t)((c8 >> 2) * 8192) + tswz(row, c8 & 3);
        const long g = (long)row*HS_ + c8*8;
        CP_A16(sb + FQHI + off, Qhg + g);
        CP_A16(sb + FQLO + off, Qlg + g);
    }
    CP_COMMIT();

    auto load_kv = [&](int kb) {
        const uint32_t st = sb + FKV + (uint32_t)(kb & 1) * KVSTAGE_B;
        const long gb = (long)kb*64*HS_;
        #pragma unroll
        for (int f = 0; f < 4; f++) {
            const int slot = tid + (f << 8);       // 0..1023
            const int row = slot >> 4, c8 = slot & 15;
            const uint32_t off = (uint32_t)((c8 >> 2) * 4096) + tswz(row, c8 & 3);
            const long g = gb + (long)row*HS_ + c8*8;
            CP_A16(st + 0     + off, Khg + g);
            CP_A16(st + 16384 + off, Klg + g);
            CP_A16(st + 32768 + off, Vhg + g);
            CP_A16(st + 49152 + off, Vlg + g);
        }
        CP_COMMIT();
    };

    // ---- adapter tiles (fp32, plain stores) ----
    {
        const float4* AKg = (const float4*)(g_AK + h*AL_*HS_);
        const float4* AVg = (const float4*)(g_AV + h*AL_*HS_);
        for (int i = tid; i < AL_*HS_/4; i += 256) {
            ((float4*)(fsm + FAK))[i] = AKg[i];
            ((float4*)(fsm + FAV))[i] = AVg[i];
        }
    }

    float O[16][4];
    #pragma unroll
    for (int nf = 0; nf < 16; nf++)
        #pragma unroll
        for (int c = 0; c < 4; c++) O[nf][c] = 0.f;
    float m0 = NEG_BIG, m1 = NEG_BIG, l0 = 0.f, l1 = 0.f;
    const float scale = 0.08838834764831843f;

    const int rowg0 = qb*128 + 16*w + rsub;
    const int warp_rmax = qb*128 + 16*w + 15;

    const int kmax = 2*qb + 2;
    load_kv(0);                                   // group 1

    for (int kb = 0; kb < kmax; kb++) {
        if (kb + 1 < kmax) load_kv(kb + 1);
        else CP_COMMIT();
        CP_WAIT(1);
        __syncthreads();

        if (kb*64 <= warp_rmax) {
            const uint32_t kvst = sb + FKV + (uint32_t)(kb & 1) * KVSTAGE_B;

            // ---- S = Q K^T ----
            float S[8][4];
            #pragma unroll
            for (int j = 0; j < 8; j++)
                #pragma unroll
                for (int c = 0; c < 4; c++) S[j][c] = 0.f;

            #pragma unroll
            for (int ks = 0; ks < 8; ks++) {
                const int tQ = ks >> 1, chb = (ks & 1) << 1;
                const int arow = 16*w + (grp & 1)*8 + lr;
                const uint32_t aoff = (uint32_t)(tQ*8192) + tswz(arow, chb + (grp >> 1));
                uint32_t ah[4], al[4];
                LDSM_X4(ah, sb + FQHI + aoff);
                LDSM_X4(al, sb + FQLO + aoff);
                #pragma unroll
                for (int jj = 0; jj < 4; jj++) {
                    const int brow = jj*16 + (grp >> 1)*8 + lr;
                    const uint32_t boff = (uint32_t)(tQ*4096) + tswz(brow, (grp & 1) + chb);
                    uint32_t kh[4], kl[4];
                    LDSM_X4(kh, kvst + 0     + boff);
                    LDSM_X4(kl, kvst + 16384 + boff);
                    #pragma unroll
                    for (int j2 = 0; j2 < 2; j2++) {
                        const int j = jj*2 + j2, jo = j2 << 1;
                        MMA_BF16(S[j], ah, kh[jo], kh[jo+1]);
                        MMA_BF16(S[j], ah, kl[jo], kl[jo+1]);
                        MMA_BF16(S[j], al, kh[jo], kh[jo+1]);
                    }
                }
            }

            // ---- scale + mask ----
            const bool needMask = (kb*64 + 63) > (qb*128 + 16*w);
            #pragma unroll
            for (int j = 0; j < 8; j++)
                #pragma unroll
                for (int c = 0; c < 4; c++) {
                    float sv = S[j][c] * scale;
                    if (needMask) {
                        const int colg = kb*64 + j*8 + 2*lam + (c & 1);
                        const int rowg = rowg0 + ((c >> 1) << 3);
                        if (colg > rowg) sv = NEG_BIG;
                    }
                    S[j][c] = sv;
                }

            // ---- online softmax ----
            float mx0 = S[0][0], mx1 = S[0][2];
            #pragma unroll
            for (int j = 0; j < 8; j++) {
                mx0 = fmaxf(mx0, fmaxf(S[j][0], S[j][1]));
                mx1 = fmaxf(mx1, fmaxf(S[j][2], S[j][3]));
            }
            mx0 = fmaxf(mx0, __shfl_xor_sync(0xffffffffu, mx0, 1));
            mx0 = fmaxf(mx0, __shfl_xor_sync(0xffffffffu, mx0, 2));
            mx1 = fmaxf(mx1, __shfl_xor_sync(0xffffffffu, mx1, 1));
            mx1 = fmaxf(mx1, __shfl_xor_sync(0xffffffffu, mx1, 2));
            const float mn0 = fmaxf(m0, mx0);
            const float mn1 = fmaxf(m1, mx1);
            const float corr0 = __expf(m0 - mn0);
            const float corr1 = __expf(m1 - mn1);
            float rs0 = 0.f, rs1 = 0.f;
            #pragma unroll
            for (int j = 0; j < 8; j++) {
                S[j][0] = __expf(S[j][0] - mn0);
                S[j][1] = __expf(S[j][1] - mn0);
                S[j][2] = __expf(S[j][2] - mn1);
                S[j][3] = __expf(S[j][3] - mn1);
                rs0 += S[j][0] + S[j][1];
                rs1 += S[j][2] + S[j][3];
            }
            l0 = l0*corr0 + rs0;
            l1 = l1*corr1 + rs1;
            m0 = mn0; m1 = mn1;
            #pragma unroll
            for (int nf = 0; nf < 16; nf++) {
                O[nf][0] *= corr0; O[nf][1] *= corr0;
                O[nf][2] *= corr1; O[nf][3] *= corr1;
            }

            // ---- O += P V ----
            #pragma unroll
            for (int ks2 = 0; ks2 < 4; ks2++) {
                const int j0 = 2*ks2, j1 = j0 + 1;
                uint32_t phi[4], plo[4];
                pack2(S[j0][0], S[j0][1], phi[0], plo[0]);
                pack2(S[j0][2], S[j0][3], phi[1], plo[1]);
                pack2(S[j1][0], S[j1][1], phi[2], plo[2]);
                pack2(S[j1][2], S[j1][3], phi[3], plo[3]);
                #pragma unroll
                for (int nc = 0; nc < 8; nc++) {
                    const int vrow = ks2*16 + (grp & 1)*8 + lr;
                    const uint32_t voff = (uint32_t)((nc >> 1) * 4096)
                                        + tswz(vrow, ((nc & 1) << 1) + (grp >> 1));
                    uint32_t vh[4], vl[4];
                    LDSM_X4_T(vh, kvst + 32768 + voff);
                    LDSM_X4_T(vl, kvst + 49152 + voff);
                    MMA_BF16(O[2*nc],   phi, vh[0], vh[1]);
                    MMA_BF16(O[2*nc+1], phi, vh[2], vh[3]);
                    MMA_BF16(O[2*nc],   phi, vl[0], vl[1]);
                    MMA_BF16(O[2*nc+1], phi, vl[2], vl[3]);
                    MMA_BF16(O[2*nc],   plo, vh[0], vh[1]);
                    MMA_BF16(O[2*nc+1], plo, vh[2], vh[3]);
                }
            }
        }
        __syncthreads();
    }

    // ---- finalize l ----
    l0 += __shfl_xor_sync(0xffffffffu, l0, 1);
    l0 += __shfl_xor_sync(0xffffffffu, l0, 2);
    l1 += __shfl_xor_sync(0xffffffffu, l1, 1);
    l1 += __shfl_xor_sync(0xffffffffu, l1, 2);

    // ---- adapter attention (q = hi+lo from smem) ----
    float sa0[AL_], sa1[AL_];
    #pragma unroll
    for (int j = 0; j < AL_; j++) { sa0[j] = 0.f; sa1[j] = 0.f; }
    const float* AKs = (const float*)(fsm + FAK);
    const float* AVs = (const float*)(fsm + FAV);
    #pragma unroll
    for (int rr = 0; rr < 2; rr++) {
        const int rowL = 16*w + rsub + rr*8;
        float* sa = rr ? sa1 : sa0;
        #pragma unroll
        for (int ch = 0; ch < 4; ch++) {
            const uint32_t off = (uint32_t)(lam * 8192) + tswz(rowL, ch);
            uint4 qh = *(const uint4*)(fsm + FQHI + off);
            uint4 ql = *(const uint4*)(fsm + FQLO + off);
            const uint32_t* qhp = (const uint32_t*)&qh;
            const uint32_t* qlp = (const uint32_t*)&ql;
            float q[8];
            #pragma unroll
            for (int e = 0; e < 4; e++) {
                __nv_bfloat162 bh2 = *reinterpret_cast<const __nv_bfloat162*>(&qhp[e]);
                __nv_bfloat162 bl2 = *reinterpret_cast<const __nv_bfloat162*>(&qlp[e]);
                q[2*e]   = __low2float(bh2)  + __low2float(bl2);
                q[2*e+1] = __high2float(bh2) + __high2float(bl2);
            }
            const int d0 = lam*32 + ch*8;
            #pragma unroll
            for (int j = 0; j < AL_; j++) {
                const float* ak = AKs + j*HS_ + d0;
                #pragma unroll
                for (int e = 0; e < 8; e++) sa[j] += q[e] * ak[e];
            }
        }
    }
    #pragma unroll
    for (int j = 0; j < AL_; j++) {
        sa0[j] += __shfl_xor_sync(0xffffffffu, sa0[j], 1);
        sa0[j] += __shfl_xor_sync(0xffffffffu, sa0[j], 2);
        sa1[j] += __shfl_xor_sync(0xffffffffu, sa1[j], 1);
        sa1[j] += __shfl_xor_sync(0xffffffffu, sa1[j], 2);
    }

    const float g = gating[h];
    #pragma unroll
    for (int rr = 0; rr < 2; rr++) {
        float* sa = rr ? sa1 : sa0;
        const float li = rr ? l1 : l0;
        const int rowg = rowg0 + rr*8;
        float mx = sa[0]*scale;
        #pragma unroll
        for (int j = 1; j < AL_; j++) mx = fmaxf(mx, sa[j]*scale);
        float pa[AL_], ssum = 0.f;
        #pragma unroll
        for (int j = 0; j < AL_; j++) { pa[j] = __expf(sa[j]*scale - mx); ssum += pa[j]; }
        const float pg = g / ssum;
        const float inv_l = 1.f / li;
        const long yidx0 = ((long)b*T_ + rowg)*C_ + h*HS_;
        #pragma unroll
        for (int nf = 0; nf < 16; nf++) {
            const int d = nf*8 + 2*lam;
            float o0 = O[nf][rr*2]   * inv_l;
            float o1 = O[nf][rr*2+1] * inv_l;
            #pragma unroll
            for (int j = 0; j < AL_; j++) {
                const float p = pa[j] * pg;
                o0 += p * AVs[j*HS_ + d];
                o1 += p * AVs[j*HS_ + d + 1];
            }
            uint32_t hi, lo; pack2(o0, o1, hi, lo);
            *(uint32_t*)((uint16_t*)g_Yh + yidx0 + d) = hi;
            *(uint32_t*)((uint16_t*)g_Yl + yidx0 + d) = lo;
        }
    }
}

// ======================================================================
extern "C" void kernel_launch(void* const* d_in, const int* in_sizes, int n_in,
                              void* d_out, int out_size)
{
    const float* x      = (const float*)d_in[0];
    const float* rope   = (const float*)d_in[1];
    const float* W_attn = (const float*)d_in[3];
    const float* W_proj = (const float*)d_in[4];
    const float* emb    = (const float*)d_in[5];
    const float* gating = (const float*)d_in[6];
    float* out = (float*)d_out;

    void *xh, *xl, *wah, *wal, *wph, *wpl, *yh, *yl;
    cudaGetSymbolAddress(&xh,  g_xh);  cudaGetSymbolAddress(&xl,  g_xl);
    cudaGetSymbolAddress(&wah, g_wah); cudaGetSymbolAddress(&wal, g_wal);
    cudaGetSymbolAddress(&wph, g_wph); cudaGetSymbolAddress(&wpl, g_wpl);
    cudaGetSymbolAddress(&yh,  g_Yh);  cudaGetSymbolAddress(&yl,  g_Yl);

    cudaFuncSetAttribute(tgemm<0>, cudaFuncAttributeMaxDynamicSharedMemorySize, GEMM_SMEM);
    cudaFuncSetAttribute(tgemm<1>, cudaFuncAttributeMaxDynamicSharedMemorySize, GEMM_SMEM);
    cudaFuncSetAttribute(flash_mma, cudaFuncAttributeMaxDynamicSharedMemorySize, FLASH_SMEM);

    // 0) split inputs into bf16 hi/lo
    {
        int n4;
        n4 = M_ROWS*KDIM/4;
        conv_split<<<(n4+255)/256, 256>>>((const float4*)x, (uint2*)xh, (uint2*)xl, n4);
        n4 = 3*C_*KDIM/4;
        conv_split<<<(n4+255)/256, 256>>>((const float4*)W_attn, (uint2*)wah, (uint2*)wal, n4);
        n4 = C_*KDIM/4;
        conv_split<<<(n4+255)/256, 256>>>((const float4*)W_proj, (uint2*)wph, (uint2*)wpl, n4);
    }
    // 1) QKV GEMM + rope -> split Q/K/V
    tgemm<0><<<dim3(48, 32), 128, GEMM_SMEM>>>(
        (const __nv_bfloat16*)xh, (const __nv_bfloat16*)xl,
        (const __nv_bfloat16*)wah, (const __nv_bfloat16*)wal, rope, nullptr);
    // 2) adapter k/v
    adapter_kv<<<4096, 128>>>(W_attn, emb);
    // 3) flash attention + fused adapter/gating -> split Y
    flash_mma<<<dim3(T_/128, B_*H_), 256, FLASH_SMEM>>>(gating);
    // 4) output projection -> fp32 out
    tgemm<1><<<dim3(16, 32), 128, GEMM_SMEM>>>(
        (const __nv_bfloat16*)yh, (const __nv_bfloat16*)yl,
        (const __nv_bfloat16*)wph, (const __nv_bfloat16*)wpl, nullptr, out);
}